// round 4
// baseline (speedup 1.0000x reference)
#include <cuda_runtime.h>
#include <math.h>

#define BB 4
#define CC 64
#define NN 4096
#define HHD 64
#define AHD 256
#define KK 16
#define RS 20   // padded row stride for k-dim smem arrays (80B rows, 16B aligned, phase-conflict-free)

// ---------------- scratch (no allocations allowed) ----------------
__device__ float g_val_t[BB * NN * CC];   // y1 (value), layout (B,N,C)
__device__ float g_key_t[BB * NN * CC];   // key, layout (B,N,C)
__device__ float g_agg[BB * NN * CC];     // aggregated features, layout (B,N,C)
__device__ int   g_idx[BB * NN * KK];     // knn indices

__device__ __forceinline__ void fma4(float4& a, float w, const float4 v) {
    a.x = fmaf(w, v.x, a.x);
    a.y = fmaf(w, v.y, a.y);
    a.z = fmaf(w, v.z, a.z);
    a.w = fmaf(w, v.w, a.w);
}

// ================= dummy kernel (shifts ncu -s 5 capture slot onto k_attn) =================
__global__ void k_dummy() {}

// ================= Kernel 1: y1 = W_start@y+b ; key = W_key@y1+b (written transposed (B,N,C)) =================
__global__ __launch_bounds__(256) void k_linear_start_key(
    const float* __restrict__ y,
    const float* __restrict__ Ws_g, const float* __restrict__ bs_g,
    const float* __restrict__ Wk_g, const float* __restrict__ bk_g)
{
    __shared__ float ys[64][64];
    __shared__ float y1s[64][64];
    __shared__ float Ws[64][64];
    int b = blockIdx.y, n0 = blockIdx.x * 64, t = threadIdx.x;

#pragma unroll
    for (int i = 0; i < 16; i++) { int e = t + i * 256; Ws[e >> 6][e & 63] = Ws_g[e]; }
#pragma unroll
    for (int i = 0; i < 16; i++) {
        int e = t + i * 256; int c = e >> 6, p = e & 63;
        ys[c][p] = y[((size_t)b * CC + c) * NN + n0 + p];
    }
    __syncthreads();

    int p = t & 63, og = t >> 6;
    float acc[16];
#pragma unroll
    for (int i = 0; i < 16; i++) acc[i] = bs_g[og * 16 + i];
#pragma unroll 4
    for (int c = 0; c < 64; c++) {
        float yv = ys[c][p];
#pragma unroll
        for (int i = 0; i < 16; i++) acc[i] = fmaf(Ws[og * 16 + i][c], yv, acc[i]);
    }
#pragma unroll
    for (int i = 0; i < 16; i++) y1s[og * 16 + i][p] = acc[i];
    {
        float4* vo = (float4*)&g_val_t[(((size_t)b * NN) + n0 + p) * CC + og * 16];
        vo[0] = make_float4(acc[0], acc[1], acc[2], acc[3]);
        vo[1] = make_float4(acc[4], acc[5], acc[6], acc[7]);
        vo[2] = make_float4(acc[8], acc[9], acc[10], acc[11]);
        vo[3] = make_float4(acc[12], acc[13], acc[14], acc[15]);
    }
    __syncthreads();
#pragma unroll
    for (int i = 0; i < 16; i++) { int e = t + i * 256; Ws[e >> 6][e & 63] = Wk_g[e]; }
    __syncthreads();
#pragma unroll
    for (int i = 0; i < 16; i++) acc[i] = bk_g[og * 16 + i];
#pragma unroll 4
    for (int c = 0; c < 64; c++) {
        float yv = y1s[c][p];
#pragma unroll
        for (int i = 0; i < 16; i++) acc[i] = fmaf(Ws[og * 16 + i][c], yv, acc[i]);
    }
    {
        float4* ko = (float4*)&g_key_t[(((size_t)b * NN) + n0 + p) * CC + og * 16];
        ko[0] = make_float4(acc[0], acc[1], acc[2], acc[3]);
        ko[1] = make_float4(acc[4], acc[5], acc[6], acc[7]);
        ko[2] = make_float4(acc[8], acc[9], acc[10], acc[11]);
        ko[3] = make_float4(acc[12], acc[13], acc[14], acc[15]);
    }
}

// ================= Kernel 2: KNN (top-16 nearest incl. self) =================
__global__ __launch_bounds__(128) void k_knn(const float* __restrict__ x)
{
    __shared__ float sxs[128], sys[128], szs[128], ssq[128];
    int b = blockIdx.y;
    int i = blockIdx.x * 128 + threadIdx.x;
    const float* xb = x + (size_t)b * 3 * NN;
    float qx = xb[i], qy = xb[NN + i], qz = xb[2 * NN + i];
    float qsq = qx * qx + qy * qy + qz * qz;

    float bd[16]; int bi[16];
#pragma unroll
    for (int s = 0; s < 16; s++) { bd[s] = 3.0e38f; bi[s] = 0; }

    for (int c0 = 0; c0 < NN; c0 += 128) {
        int j = c0 + threadIdx.x;
        float a0 = xb[j], a1 = xb[NN + j], a2 = xb[2 * NN + j];
        sxs[threadIdx.x] = a0; sys[threadIdx.x] = a1; szs[threadIdx.x] = a2;
        ssq[threadIdx.x] = a0 * a0 + a1 * a1 + a2 * a2;
        __syncthreads();
#pragma unroll 4
        for (int jj = 0; jj < 128; jj++) {
            float dot = qx * sxs[jj] + qy * sys[jj] + qz * szs[jj];
            float d = qsq - 2.0f * dot + ssq[jj];
            if (d < bd[15]) {
                bd[15] = d; bi[15] = c0 + jj;
#pragma unroll
                for (int s = 15; s > 0; --s) {
                    if (bd[s] < bd[s - 1]) {
                        float td = bd[s]; bd[s] = bd[s - 1]; bd[s - 1] = td;
                        int ti = bi[s]; bi[s] = bi[s - 1]; bi[s - 1] = ti;
                    } else break;
                }
            }
        }
        __syncthreads();
    }
#pragma unroll
    for (int s = 0; s < 16; s++) g_idx[((size_t)b * NN + i) * KK + s] = bi[s];
}

// ================= Kernel 3: fused attention (register-blocked, 256 threads) =================
struct __align__(16) S3 {
    float A1s[64][256];     // [c][a], BN-folded, aligned for float4 over a
    float A2s[256][64];     // [h][c], aligned for float2/float4 over c
    float P2s[64][64];      // [h][c]
    float h1s[2][256][RS];
    float th[2][64][RS];    // pe hidden, then attn logits
    float kgu[2][64][RS];   // gathered key, then u = (q-key)+pe in place
    float pes[2][64][RS];   // stores val + pe  (used directly in stage 6)
    float P1p[64][3];
    float Wq[64][3];
    float b1p[256];
    float s2s[256];
    float pb1p[64];
    float s1s[64];
    float pb2s[64];
    float ab2s[64];
    float bqs[64];
    float posr[2][3][16];
    float qy[2][64];
    float vals[2][64];
};

__global__ void __launch_bounds__(256, 1) k_attn(
    const float* __restrict__ x,
    const float* __restrict__ Wq_g, const float* __restrict__ bq_g,
    const float* __restrict__ P1, const float* __restrict__ pb1,
    const float* __restrict__ bn1_g, const float* __restrict__ bn1_b,
    const float* __restrict__ bn1_m, const float* __restrict__ bn1_v,
    const float* __restrict__ P2, const float* __restrict__ pb2,
    const float* __restrict__ A1, const float* __restrict__ ab1,
    const float* __restrict__ bn2_g, const float* __restrict__ bn2_b,
    const float* __restrict__ bn2_m, const float* __restrict__ bn2_v,
    const float* __restrict__ A2, const float* __restrict__ ab2)
{
    extern __shared__ char smraw[];
    S3& s = *(S3*)smraw;
    int t = threadIdx.x;
    int b = blockIdx.x >> 9;
    int n_base = (blockIdx.x & 511) * 8;

    // ---- fold BN into weights/biases ----
    {
        float s2 = bn2_g[t] / sqrtf(bn2_v[t] + 1e-5f);
        s.s2s[t] = s2;
        s.b1p[t] = (ab1[t] - bn2_m[t]) * s2 + bn2_b[t];
    }
    if (t < 64) {
        float s1 = bn1_g[t] / sqrtf(bn1_v[t] + 1e-5f);
        s.s1s[t] = s1;
        s.pb1p[t] = (pb1[t] - bn1_m[t]) * s1 + bn1_b[t];
        s.pb2s[t] = pb2[t];
        s.ab2s[t] = ab2[t];
        s.bqs[t] = bq_g[t];
    }
    if (t < 192) s.Wq[t / 3][t % 3] = Wq_g[t];
    __syncthreads();
    if (t < 192) s.P1p[t / 3][t % 3] = P1[t] * s.s1s[t / 3];
    // A1s[c][a] = A1[a][c] * s2[a]   (writes contiguous in a)
#pragma unroll
    for (int i = 0; i < 64; i++) {
        int e = t + i * 256; int c = e >> 8, a = e & 255;
        s.A1s[c][a] = A1[a * 64 + c] * s.s2s[a];
    }
    // A2s[h][c] = A2[c][h]   (writes contiguous in c)
#pragma unroll
    for (int i = 0; i < 64; i++) {
        int e = t + i * 256; int h = e >> 6, c = e & 63;
        s.A2s[h][c] = A2[c * 256 + h];
    }
    // P2s[h][c] = P2[c][h]
#pragma unroll
    for (int i = 0; i < 16; i++) {
        int e = t + i * 256; int h = e >> 6, c = e & 63;
        s.P2s[h][c] = P2[c * 64 + h];
    }
    __syncthreads();

    const float* xb = x + (size_t)b * 3 * NN;
    const int* idxb = &g_idx[(size_t)b * NN * KK];

    for (int pp = 0; pp < 8; pp += 2) {
        int n0 = n_base + pp;

        // ---- stage 0: gathers / small linears ----
        if (t < 96) {
            int pt = t / 48, r = t % 48, d = r >> 4, k = r & 15;
            int j = idxb[(n0 + pt) * KK + k];
            s.posr[pt][d][k] = xb[d * NN + n0 + pt] - xb[d * NN + j];
        } else if (t >= 128) {
            int tt = t - 128, pt = tt >> 6, c = tt & 63;
            int n = n0 + pt;
            s.qy[pt][c] = s.bqs[c] + s.Wq[c][0] * xb[n] + s.Wq[c][1] * xb[NN + n] + s.Wq[c][2] * xb[2 * NN + n];
        }
        if (t < 128) {
            int pt = t >> 6, c = t & 63;
            s.vals[pt][c] = g_val_t[((size_t)b * NN + n0 + pt) * CC + c];
        }
        {   // key gather (contiguous 256B per neighbor in transposed layout)
            int pt = t >> 7, r = t & 127, c8 = r >> 4, k = r & 15;
            int j = idxb[(n0 + pt) * KK + k];
            const float4* kp = (const float4*)&g_key_t[((size_t)b * NN + j) * CC + c8 * 8];
            float4 v0 = kp[0], v1 = kp[1];
            int cb = c8 * 8;
            s.kgu[pt][cb + 0][k] = v0.x; s.kgu[pt][cb + 1][k] = v0.y;
            s.kgu[pt][cb + 2][k] = v0.z; s.kgu[pt][cb + 3][k] = v0.w;
            s.kgu[pt][cb + 4][k] = v1.x; s.kgu[pt][cb + 5][k] = v1.y;
            s.kgu[pt][cb + 6][k] = v1.z; s.kgu[pt][cb + 7][k] = v1.w;
        }
        __syncthreads();

        // ---- stage 1: th = relu(P1'@pos_rel + pb1') ----
        {
            int h = t & 63, kg = t >> 6;
#pragma unroll
            for (int pt = 0; pt < 2; pt++) {
                float4 o;
                float* ov = (float*)&o;
#pragma unroll
                for (int kk = 0; kk < 4; kk++) {
                    int k = kg * 4 + kk;
                    float a = s.pb1p[h]
                            + s.P1p[h][0] * s.posr[pt][0][k]
                            + s.P1p[h][1] * s.posr[pt][1][k]
                            + s.P1p[h][2] * s.posr[pt][2][k];
                    ov[kk] = fmaxf(a, 0.0f);
                }
                *(float4*)&s.th[pt][h][kg * 4] = o;
            }
        }
        __syncthreads();

        // ---- stage 2+3: pe = P2@th + pb2 ; u = (q - key) + pe ; vpe = val + pe ----
        {
            int pt = t >> 7, cg = (t >> 2) & 31, kg = t & 3;
            int c0 = cg * 2;
            float4 a0 = make_float4(s.pb2s[c0], s.pb2s[c0], s.pb2s[c0], s.pb2s[c0]);
            float4 a1 = make_float4(s.pb2s[c0 + 1], s.pb2s[c0 + 1], s.pb2s[c0 + 1], s.pb2s[c0 + 1]);
#pragma unroll 4
            for (int h = 0; h < 64; h++) {
                float2 w = *(const float2*)&s.P2s[h][c0];
                float4 tv = *(const float4*)&s.th[pt][h][kg * 4];
                fma4(a0, w.x, tv);
                fma4(a1, w.y, tv);
            }
            float q0 = s.qy[pt][c0], q1 = s.qy[pt][c0 + 1];
            float v0 = s.vals[pt][c0], v1 = s.vals[pt][c0 + 1];
            float4 kv0 = *(const float4*)&s.kgu[pt][c0][kg * 4];
            float4 kv1 = *(const float4*)&s.kgu[pt][c0 + 1][kg * 4];
            float4 u0, u1, w0, w1;
            u0.x = (q0 - kv0.x) + a0.x; u0.y = (q0 - kv0.y) + a0.y;
            u0.z = (q0 - kv0.z) + a0.z; u0.w = (q0 - kv0.w) + a0.w;
            u1.x = (q1 - kv1.x) + a1.x; u1.y = (q1 - kv1.y) + a1.y;
            u1.z = (q1 - kv1.z) + a1.z; u1.w = (q1 - kv1.w) + a1.w;
            w0.x = v0 + a0.x; w0.y = v0 + a0.y; w0.z = v0 + a0.z; w0.w = v0 + a0.w;
            w1.x = v1 + a1.x; w1.y = v1 + a1.y; w1.z = v1 + a1.z; w1.w = v1 + a1.w;
            *(float4*)&s.kgu[pt][c0][kg * 4] = u0;
            *(float4*)&s.kgu[pt][c0 + 1][kg * 4] = u1;
            *(float4*)&s.pes[pt][c0][kg * 4] = w0;
            *(float4*)&s.pes[pt][c0 + 1][kg * 4] = w1;
        }
        __syncthreads();

        // ---- stage 4: h1 = relu(A1'@u + b1')  — 4a x 4k x 2pt register tile ----
        {
            int ag = t >> 2, kg = t & 3;
            int a0 = ag * 4;
            float4 acc0[4], acc1[4];
#pragma unroll
            for (int i = 0; i < 4; i++) {
                float bb = s.b1p[a0 + i];
                acc0[i] = make_float4(bb, bb, bb, bb);
                acc1[i] = acc0[i];
            }
#pragma unroll 4
            for (int c = 0; c < 64; c++) {
                float4 w = *(const float4*)&s.A1s[c][a0];
                float4 u0 = *(const float4*)&s.kgu[0][c][kg * 4];
                float4 u1 = *(const float4*)&s.kgu[1][c][kg * 4];
                fma4(acc0[0], w.x, u0); fma4(acc1[0], w.x, u1);
                fma4(acc0[1], w.y, u0); fma4(acc1[1], w.y, u1);
                fma4(acc0[2], w.z, u0); fma4(acc1[2], w.z, u1);
                fma4(acc0[3], w.w, u0); fma4(acc1[3], w.w, u1);
            }
#pragma unroll
            for (int i = 0; i < 4; i++) {
                float4 v = acc0[i];
                v.x = fmaxf(v.x, 0.0f); v.y = fmaxf(v.y, 0.0f);
                v.z = fmaxf(v.z, 0.0f); v.w = fmaxf(v.w, 0.0f);
                *(float4*)&s.h1s[0][a0 + i][kg * 4] = v;
                float4 u = acc1[i];
                u.x = fmaxf(u.x, 0.0f); u.y = fmaxf(u.y, 0.0f);
                u.z = fmaxf(u.z, 0.0f); u.w = fmaxf(u.w, 0.0f);
                *(float4*)&s.h1s[1][a0 + i][kg * 4] = u;
            }
        }
        __syncthreads();

        // ---- stage 5: logits = A2@h1 + ab2  — 2c x 4k register tile (into th) ----
        {
            int pt = t >> 7, cg = (t >> 2) & 31, kg = t & 3;
            int c0 = cg * 2;
            float4 a0 = make_float4(s.ab2s[c0], s.ab2s[c0], s.ab2s[c0], s.ab2s[c0]);
            float4 a1 = make_float4(s.ab2s[c0 + 1], s.ab2s[c0 + 1], s.ab2s[c0 + 1], s.ab2s[c0 + 1]);
#pragma unroll 8
            for (int h = 0; h < 256; h++) {
                float2 w = *(const float2*)&s.A2s[h][c0];
                float4 hv = *(const float4*)&s.h1s[pt][h][kg * 4];
                fma4(a0, w.x, hv);
                fma4(a1, w.y, hv);
            }
            *(float4*)&s.th[pt][c0][kg * 4] = a0;
            *(float4*)&s.th[pt][c0 + 1][kg * 4] = a1;
        }
        __syncthreads();

        // ---- stage 6: softmax over k + aggregate (pes already holds val+pe) ----
        if (t < 128) {
            int pt = t >> 6, c = t & 63;
            float av[16], vp[16];
#pragma unroll
            for (int g = 0; g < 4; g++) {
                float4 v = *(const float4*)&s.th[pt][c][g * 4];
                av[g * 4 + 0] = v.x; av[g * 4 + 1] = v.y;
                av[g * 4 + 2] = v.z; av[g * 4 + 3] = v.w;
                float4 w = *(const float4*)&s.pes[pt][c][g * 4];
                vp[g * 4 + 0] = w.x; vp[g * 4 + 1] = w.y;
                vp[g * 4 + 2] = w.z; vp[g * 4 + 3] = w.w;
            }
            float m = av[0];
#pragma unroll
            for (int k = 1; k < 16; k++) m = fmaxf(m, av[k]);
            float vsum = 0.0f, acc = 0.0f;
#pragma unroll
            for (int k = 0; k < 16; k++) {
                float e = __expf(av[k] - m);
                vsum += e;
                acc = fmaf(e, vp[k], acc);
            }
            g_agg[((size_t)b * NN + n0 + pt) * CC + c] = acc / vsum;
        }
        __syncthreads();
    }
}

// ================= Kernel 4: out = W_end @ agg + b_end + y =================
__global__ __launch_bounds__(256) void k_end(
    const float* __restrict__ y, const float* __restrict__ We_g,
    const float* __restrict__ be_g, float* __restrict__ out)
{
    __shared__ float As[64][65];
    __shared__ float Ws[64][64];
    int b = blockIdx.y, n0 = blockIdx.x * 64, t = threadIdx.x;
#pragma unroll
    for (int i = 0; i < 16; i++) { int e = t + i * 256; Ws[e >> 6][e & 63] = We_g[e]; }
#pragma unroll
    for (int i = 0; i < 16; i++) {
        int e = t + i * 256; int p = e >> 6, c = e & 63;
        As[p][c] = g_agg[((size_t)b * NN + n0 + p) * CC + c];
    }
    __syncthreads();
    int p = t & 63, og = t >> 6;
    float acc[16];
#pragma unroll
    for (int i = 0; i < 16; i++) acc[i] = be_g[og * 16 + i];
#pragma unroll 4
    for (int c = 0; c < 64; c++) {
        float av = As[p][c];
#pragma unroll
        for (int i = 0; i < 16; i++) acc[i] = fmaf(Ws[og * 16 + i][c], av, acc[i]);
    }
#pragma unroll
    for (int i = 0; i < 16; i++) {
        int o = og * 16 + i;
        size_t off = ((size_t)b * CC + o) * NN + n0 + p;
        out[off] = acc[i] + y[off];
    }
}

// ================= launcher =================
extern "C" void kernel_launch(void* const* d_in, const int* in_sizes, int n_in,
                              void* d_out, int out_size)
{
    const float* x       = (const float*)d_in[0];
    const float* y       = (const float*)d_in[1];
    const float* W_start = (const float*)d_in[2];
    const float* b_start = (const float*)d_in[3];
    const float* W_key   = (const float*)d_in[4];
    const float* b_key   = (const float*)d_in[5];
    const float* W_query = (const float*)d_in[6];
    const float* b_query = (const float*)d_in[7];
    const float* P1      = (const float*)d_in[8];
    const float* pb1     = (const float*)d_in[9];
    const float* bn1_g   = (const float*)d_in[10];
    const float* bn1_b   = (const float*)d_in[11];
    const float* bn1_m   = (const float*)d_in[12];
    const float* bn1_v   = (const float*)d_in[13];
    const float* P2      = (const float*)d_in[14];
    const float* pb2     = (const float*)d_in[15];
    const float* A1      = (const float*)d_in[16];
    const float* ab1     = (const float*)d_in[17];
    const float* bn2_g   = (const float*)d_in[18];
    const float* bn2_b   = (const float*)d_in[19];
    const float* bn2_m   = (const float*)d_in[20];
    const float* bn2_v   = (const float*)d_in[21];
    const float* A2      = (const float*)d_in[22];
    const float* ab2     = (const float*)d_in[23];
    const float* W_end   = (const float*)d_in[24];
    const float* b_end   = (const float*)d_in[25];

    cudaFuncSetAttribute(k_attn, cudaFuncAttributeMaxDynamicSharedMemorySize, (int)sizeof(S3));

    k_dummy<<<1, 32>>>();   // slot-shift so ncu -s 5 lands on k_attn
    k_linear_start_key<<<dim3(NN / 64, BB), 256>>>(y, W_start, b_start, W_key, b_key);
    k_knn<<<dim3(NN / 128, BB), 128>>>(x);
    k_attn<<<BB * NN / 8, 256, sizeof(S3)>>>(x, W_query, b_query,
                                             P1, pb1, bn1_g, bn1_b, bn1_m, bn1_v,
                                             P2, pb2, A1, ab1,
                                             bn2_g, bn2_b, bn2_m, bn2_v, A2, ab2);
    k_end<<<dim3(NN / 64, BB), 256>>>(y, W_end, b_end, (float*)d_out);
}

// round 5
// speedup vs baseline: 1.9194x; 1.9194x over previous
#include <cuda_runtime.h>
#include <math.h>

#define BB 4
#define CC 64
#define NN 4096
#define KK 16

// ---------------- scratch (no allocations allowed) ----------------
__device__ float g_val_t[BB * NN * CC];   // y1 (value), layout (B,N,C)
__device__ float g_key_t[BB * NN * CC];   // key, layout (B,N,C)
__device__ float g_agg[BB * NN * CC];     // aggregated features, layout (B,N,C)
__device__ int   g_idx[BB * NN * KK];     // knn indices

__device__ __forceinline__ void fma4(float4& a, float w, const float4 v) {
    a.x = fmaf(w, v.x, a.x);
    a.y = fmaf(w, v.y, a.y);
    a.z = fmaf(w, v.z, a.z);
    a.w = fmaf(w, v.w, a.w);
}

// ================= dummy kernel (shifts ncu -s 5 capture slot onto k_attn) =================
__global__ void k_dummy() {}

// ================= Kernel 1: y1 = W_start@y+b ; key = W_key@y1+b (written transposed (B,N,C)) =================
__global__ __launch_bounds__(256) void k_linear_start_key(
    const float* __restrict__ y,
    const float* __restrict__ Ws_g, const float* __restrict__ bs_g,
    const float* __restrict__ Wk_g, const float* __restrict__ bk_g)
{
    __shared__ float ys[64][64];
    __shared__ float y1s[64][64];
    __shared__ float Ws[64][64];
    int b = blockIdx.y, n0 = blockIdx.x * 64, t = threadIdx.x;

#pragma unroll
    for (int i = 0; i < 16; i++) { int e = t + i * 256; Ws[e >> 6][e & 63] = Ws_g[e]; }
#pragma unroll
    for (int i = 0; i < 16; i++) {
        int e = t + i * 256; int c = e >> 6, p = e & 63;
        ys[c][p] = y[((size_t)b * CC + c) * NN + n0 + p];
    }
    __syncthreads();

    int p = t & 63, og = t >> 6;
    float acc[16];
#pragma unroll
    for (int i = 0; i < 16; i++) acc[i] = bs_g[og * 16 + i];
#pragma unroll 4
    for (int c = 0; c < 64; c++) {
        float yv = ys[c][p];
#pragma unroll
        for (int i = 0; i < 16; i++) acc[i] = fmaf(Ws[og * 16 + i][c], yv, acc[i]);
    }
#pragma unroll
    for (int i = 0; i < 16; i++) y1s[og * 16 + i][p] = acc[i];
    {
        float4* vo = (float4*)&g_val_t[(((size_t)b * NN) + n0 + p) * CC + og * 16];
        vo[0] = make_float4(acc[0], acc[1], acc[2], acc[3]);
        vo[1] = make_float4(acc[4], acc[5], acc[6], acc[7]);
        vo[2] = make_float4(acc[8], acc[9], acc[10], acc[11]);
        vo[3] = make_float4(acc[12], acc[13], acc[14], acc[15]);
    }
    __syncthreads();
#pragma unroll
    for (int i = 0; i < 16; i++) { int e = t + i * 256; Ws[e >> 6][e & 63] = Wk_g[e]; }
    __syncthreads();
#pragma unroll
    for (int i = 0; i < 16; i++) acc[i] = bk_g[og * 16 + i];
#pragma unroll 4
    for (int c = 0; c < 64; c++) {
        float yv = y1s[c][p];
#pragma unroll
        for (int i = 0; i < 16; i++) acc[i] = fmaf(Ws[og * 16 + i][c], yv, acc[i]);
    }
    {
        float4* ko = (float4*)&g_key_t[(((size_t)b * NN) + n0 + p) * CC + og * 16];
        ko[0] = make_float4(acc[0], acc[1], acc[2], acc[3]);
        ko[1] = make_float4(acc[4], acc[5], acc[6], acc[7]);
        ko[2] = make_float4(acc[8], acc[9], acc[10], acc[11]);
        ko[3] = make_float4(acc[12], acc[13], acc[14], acc[15]);
    }
}

// ================= Kernel 2: KNN (top-16 nearest incl. self) =================
__global__ __launch_bounds__(128) void k_knn(const float* __restrict__ x)
{
    __shared__ float sxs[128], sys[128], szs[128], ssq[128];
    int b = blockIdx.y;
    int i = blockIdx.x * 128 + threadIdx.x;
    const float* xb = x + (size_t)b * 3 * NN;
    float qx = xb[i], qy = xb[NN + i], qz = xb[2 * NN + i];
    float qsq = qx * qx + qy * qy + qz * qz;

    float bd[16]; int bi[16];
#pragma unroll
    for (int s = 0; s < 16; s++) { bd[s] = 3.0e38f; bi[s] = 0; }

    for (int c0 = 0; c0 < NN; c0 += 128) {
        int j = c0 + threadIdx.x;
        float a0 = xb[j], a1 = xb[NN + j], a2 = xb[2 * NN + j];
        sxs[threadIdx.x] = a0; sys[threadIdx.x] = a1; szs[threadIdx.x] = a2;
        ssq[threadIdx.x] = a0 * a0 + a1 * a1 + a2 * a2;
        __syncthreads();
#pragma unroll 4
        for (int jj = 0; jj < 128; jj++) {
            float dot = qx * sxs[jj] + qy * sys[jj] + qz * szs[jj];
            float d = qsq - 2.0f * dot + ssq[jj];
            if (d < bd[15]) {
                bd[15] = d; bi[15] = c0 + jj;
#pragma unroll
                for (int s = 15; s > 0; --s) {
                    if (bd[s] < bd[s - 1]) {
                        float td = bd[s]; bd[s] = bd[s - 1]; bd[s - 1] = td;
                        int ti = bi[s]; bi[s] = bi[s - 1]; bi[s - 1] = ti;
                    } else break;
                }
            }
        }
        __syncthreads();
    }
#pragma unroll
    for (int s = 0; s < 16; s++) g_idx[((size_t)b * NN + i) * KK + s] = bi[s];
}

// ================= Kernel 3: fused attention, edge-contiguous layout, 4 points/iter =================
// Activation arrays are [row][edge] with edge = pt*16+k contiguous (stride 68 = 4*17,
// float4-aligned, row-to-row bank shift 4). All hot LDS are row-contiguous unique data.
struct __align__(16) S3 {
    float A1s[64][260];     // [c][a], BN-folded A1 (260 = 4*65: float4-aligned rows)
    float A2s[256][68];     // [h][c]
    float P2s[64][68];      // [h][c]
    float h1s[128][68];     // one h-half of h1, rows = h within half
    float th[64][68];       // P1-hidden [h][e] -> pe [c][e]
    float kgu[64][68];      // key [c][e] -> u [c][e] -> logits [c][e]
    float P1p[64][3];
    float Wq[64][3];
    float b1p[256];
    float s2s[256];
    float s1s[64];
    float pb1p[64];
    float pb2s[64];
    float ab2s[64];
    float bqs[64];
    float posr[4][3][16];
    float qy[4][64];
    float vals[4][64];
};

__global__ void __launch_bounds__(256, 1) k_attn(
    const float* __restrict__ x,
    const float* __restrict__ Wq_g, const float* __restrict__ bq_g,
    const float* __restrict__ P1, const float* __restrict__ pb1,
    const float* __restrict__ bn1_g, const float* __restrict__ bn1_b,
    const float* __restrict__ bn1_m, const float* __restrict__ bn1_v,
    const float* __restrict__ P2, const float* __restrict__ pb2,
    const float* __restrict__ A1, const float* __restrict__ ab1,
    const float* __restrict__ bn2_g, const float* __restrict__ bn2_b,
    const float* __restrict__ bn2_m, const float* __restrict__ bn2_v,
    const float* __restrict__ A2, const float* __restrict__ ab2)
{
    extern __shared__ char smraw[];
    S3& s = *(S3*)smraw;
    int t = threadIdx.x;
    int b = blockIdx.x >> 9;               // 512 tiles of 8 points per batch
    int n_base = (blockIdx.x & 511) * 8;

    // ---- fold BN into weights/biases, stage weights to smem ----
    {
        float s2 = bn2_g[t] / sqrtf(bn2_v[t] + 1e-5f);
        s.s2s[t] = s2;
        s.b1p[t] = (ab1[t] - bn2_m[t]) * s2 + bn2_b[t];
    }
    if (t < 64) {
        float s1 = bn1_g[t] / sqrtf(bn1_v[t] + 1e-5f);
        s.s1s[t] = s1;
        s.pb1p[t] = (pb1[t] - bn1_m[t]) * s1 + bn1_b[t];
        s.pb2s[t] = pb2[t];
        s.ab2s[t] = ab2[t];
        s.bqs[t] = bq_g[t];
    }
    if (t < 192) s.Wq[t / 3][t % 3] = Wq_g[t];
    __syncthreads();
    if (t < 192) s.P1p[t / 3][t % 3] = P1[t] * s.s1s[t / 3];
#pragma unroll
    for (int i = 0; i < 64; i++) {
        int e = t + i * 256; int a = e >> 6, c = e & 63;
        s.A1s[c][a] = A1[e] * s.s2s[a];
    }
#pragma unroll
    for (int i = 0; i < 64; i++) {
        int e = t + i * 256; int c = e >> 8, h = e & 255;
        s.A2s[h][c] = A2[e];
    }
#pragma unroll
    for (int i = 0; i < 16; i++) {
        int e = t + i * 256; int c = e >> 6, h = e & 63;
        s.P2s[h][c] = P2[e];
    }
    __syncthreads();

    const float* xb = x + (size_t)b * 3 * NN;
    const int* idxb = &g_idx[(size_t)b * NN * KK];

    // per-thread stage identities
    const int cg2 = t >> 4, eg2 = t & 15;         // stage 2/5: 4c x 4e tile
    const int c20 = cg2 * 4, e20 = eg2 * 4;
    const int ag = t >> 3, eg4 = t & 7;           // stage 4: 4a x 8e tile
    const int a0r = ag * 4, e40 = eg4 * 8;
    const int pt6 = t >> 6, c6 = t & 63;          // stage 0b/6: (pt, c)

    for (int pp = 0; pp < 8; pp += 4) {
        int n0 = n_base + pp;

        // ---- stage 0: key gather (kgu <- key), posr, qy, vals ----
        {
            int e = t & 63, cq = t >> 6;
            int pt = e >> 4, k = e & 15;
            int j = idxb[(n0 + pt) * KK + k];
            const float4* kp = (const float4*)&g_key_t[((size_t)b * NN + j) * CC + cq * 16];
            float4 v0 = kp[0], v1 = kp[1], v2 = kp[2], v3 = kp[3];
            int cb = cq * 16;
            s.kgu[cb + 0][e] = v0.x;  s.kgu[cb + 1][e] = v0.y;
            s.kgu[cb + 2][e] = v0.z;  s.kgu[cb + 3][e] = v0.w;
            s.kgu[cb + 4][e] = v1.x;  s.kgu[cb + 5][e] = v1.y;
            s.kgu[cb + 6][e] = v1.z;  s.kgu[cb + 7][e] = v1.w;
            s.kgu[cb + 8][e] = v2.x;  s.kgu[cb + 9][e] = v2.y;
            s.kgu[cb + 10][e] = v2.z; s.kgu[cb + 11][e] = v2.w;
            s.kgu[cb + 12][e] = v3.x; s.kgu[cb + 13][e] = v3.y;
            s.kgu[cb + 14][e] = v3.z; s.kgu[cb + 15][e] = v3.w;
        }
        if (t < 192) {
            int pt = t / 48, r = t % 48, d = r >> 4, k = r & 15;
            int j = idxb[(n0 + pt) * KK + k];
            s.posr[pt][d][k] = xb[d * NN + n0 + pt] - xb[d * NN + j];
        }
        {
            int n = n0 + pt6;
            s.qy[pt6][c6] = s.bqs[c6] + s.Wq[c6][0] * xb[n] + s.Wq[c6][1] * xb[NN + n]
                          + s.Wq[c6][2] * xb[2 * NN + n];
            s.vals[pt6][c6] = g_val_t[((size_t)b * NN + n) * CC + c6];
        }
        __syncthreads();

        // ---- stage 1: th[h][e] = relu(P1'@pos_rel + pb1') ----
        {
            int h = t & 63, pt = t >> 6;
            float p0 = s.P1p[h][0], p1 = s.P1p[h][1], p2 = s.P1p[h][2], bb = s.pb1p[h];
#pragma unroll
            for (int g = 0; g < 4; g++) {
                float4 o;
                float* ov = (float*)&o;
#pragma unroll
                for (int kk = 0; kk < 4; kk++) {
                    int k = g * 4 + kk;
                    float a = bb + p0 * s.posr[pt][0][k] + p1 * s.posr[pt][1][k]
                                 + p2 * s.posr[pt][2][k];
                    ov[kk] = fmaxf(a, 0.0f);
                }
                *(float4*)&s.th[h][pt * 16 + g * 4] = o;
            }
        }
        __syncthreads();

        // ---- stage 2: pe = P2@th + pb2 (4c x 4e per-thread tile, all-unique LDS) ----
        float4 pa0, pa1, pa2, pa3;
        {
            float b0 = s.pb2s[c20], b1 = s.pb2s[c20 + 1], b2 = s.pb2s[c20 + 2], b3 = s.pb2s[c20 + 3];
            pa0 = make_float4(b0, b0, b0, b0);
            pa1 = make_float4(b1, b1, b1, b1);
            pa2 = make_float4(b2, b2, b2, b2);
            pa3 = make_float4(b3, b3, b3, b3);
#pragma unroll 4
            for (int h = 0; h < 64; h++) {
                float4 w = *(const float4*)&s.P2s[h][c20];
                float4 tv = *(const float4*)&s.th[h][e20];
                fma4(pa0, w.x, tv); fma4(pa1, w.y, tv);
                fma4(pa2, w.z, tv); fma4(pa3, w.w, tv);
            }
        }
        __syncthreads();   // all reads of th (hidden) complete
        // ---- stage 2b: th <- pe ; kgu <- u = (q - key) + pe ----
        {
            int pt = e20 >> 4;
            float q0 = s.qy[pt][c20], q1 = s.qy[pt][c20 + 1];
            float q2 = s.qy[pt][c20 + 2], q3 = s.qy[pt][c20 + 3];
            float4 k0 = *(const float4*)&s.kgu[c20][e20];
            float4 k1 = *(const float4*)&s.kgu[c20 + 1][e20];
            float4 k2 = *(const float4*)&s.kgu[c20 + 2][e20];
            float4 k3 = *(const float4*)&s.kgu[c20 + 3][e20];
            *(float4*)&s.th[c20][e20] = pa0;
            *(float4*)&s.th[c20 + 1][e20] = pa1;
            *(float4*)&s.th[c20 + 2][e20] = pa2;
            *(float4*)&s.th[c20 + 3][e20] = pa3;
            float4 u;
            u.x = (q0 - k0.x) + pa0.x; u.y = (q0 - k0.y) + pa0.y;
            u.z = (q0 - k0.z) + pa0.z; u.w = (q0 - k0.w) + pa0.w;
            *(float4*)&s.kgu[c20][e20] = u;
            u.x = (q1 - k1.x) + pa1.x; u.y = (q1 - k1.y) + pa1.y;
            u.z = (q1 - k1.z) + pa1.z; u.w = (q1 - k1.w) + pa1.w;
            *(float4*)&s.kgu[c20 + 1][e20] = u;
            u.x = (q2 - k2.x) + pa2.x; u.y = (q2 - k2.y) + pa2.y;
            u.z = (q2 - k2.z) + pa2.z; u.w = (q2 - k2.w) + pa2.w;
            *(float4*)&s.kgu[c20 + 2][e20] = u;
            u.x = (q3 - k3.x) + pa3.x; u.y = (q3 - k3.y) + pa3.y;
            u.z = (q3 - k3.z) + pa3.z; u.w = (q3 - k3.w) + pa3.w;
            *(float4*)&s.kgu[c20 + 3][e20] = u;
        }
        __syncthreads();

        // ---- stages 4+5 over two h-halves; stage-5 accumulators persist in regs ----
        float4 L0, L1, L2, L3;
        {
            float b0 = s.ab2s[c20], b1 = s.ab2s[c20 + 1], b2 = s.ab2s[c20 + 2], b3 = s.ab2s[c20 + 3];
            L0 = make_float4(b0, b0, b0, b0);
            L1 = make_float4(b1, b1, b1, b1);
            L2 = make_float4(b2, b2, b2, b2);
            L3 = make_float4(b3, b3, b3, b3);
        }
#pragma unroll
        for (int r = 0; r < 2; r++) {
            // stage 4: h1[half] = relu(A1'@u + b1')  (4a x 8e tile)
            {
                int abase = r * 128 + a0r;
                float b0 = s.b1p[abase], b1 = s.b1p[abase + 1];
                float b2 = s.b1p[abase + 2], b3 = s.b1p[abase + 3];
                float4 A00 = make_float4(b0, b0, b0, b0), A01 = A00;
                float4 A10 = make_float4(b1, b1, b1, b1), A11 = A10;
                float4 A20 = make_float4(b2, b2, b2, b2), A21 = A20;
                float4 A30 = make_float4(b3, b3, b3, b3), A31 = A30;
#pragma unroll 4
                for (int c = 0; c < 64; c++) {
                    float4 w = *(const float4*)&s.A1s[c][abase];
                    float4 u0 = *(const float4*)&s.kgu[c][e40];
                    float4 u1 = *(const float4*)&s.kgu[c][e40 + 4];
                    fma4(A00, w.x, u0); fma4(A01, w.x, u1);
                    fma4(A10, w.y, u0); fma4(A11, w.y, u1);
                    fma4(A20, w.z, u0); fma4(A21, w.z, u1);
                    fma4(A30, w.w, u0); fma4(A31, w.w, u1);
                }
#define RELU4(v) v.x = fmaxf(v.x, 0.f); v.y = fmaxf(v.y, 0.f); v.z = fmaxf(v.z, 0.f); v.w = fmaxf(v.w, 0.f);
                RELU4(A00) RELU4(A01) RELU4(A10) RELU4(A11)
                RELU4(A20) RELU4(A21) RELU4(A30) RELU4(A31)
#undef RELU4
                *(float4*)&s.h1s[a0r][e40] = A00;     *(float4*)&s.h1s[a0r][e40 + 4] = A01;
                *(float4*)&s.h1s[a0r + 1][e40] = A10; *(float4*)&s.h1s[a0r + 1][e40 + 4] = A11;
                *(float4*)&s.h1s[a0r + 2][e40] = A20; *(float4*)&s.h1s[a0r + 2][e40 + 4] = A21;
                *(float4*)&s.h1s[a0r + 3][e40] = A30; *(float4*)&s.h1s[a0r + 3][e40 + 4] = A31;
            }
            __syncthreads();
            // stage 5 partial: logits += A2[:, half]@h1[half]  (4c x 4e tile)
#pragma unroll 4
            for (int j = 0; j < 128; j++) {
                float4 w = *(const float4*)&s.A2s[r * 128 + j][c20];
                float4 hv = *(const float4*)&s.h1s[j][e20];
                fma4(L0, w.x, hv); fma4(L1, w.y, hv);
                fma4(L2, w.z, hv); fma4(L3, w.w, hv);
            }
            __syncthreads();   // h1 reads done before overwrite (r=0) / before logit write (r=1)
        }
        // write logits into kgu (u is dead)
        *(float4*)&s.kgu[c20][e20] = L0;
        *(float4*)&s.kgu[c20 + 1][e20] = L1;
        *(float4*)&s.kgu[c20 + 2][e20] = L2;
        *(float4*)&s.kgu[c20 + 3][e20] = L3;
        __syncthreads();

        // ---- stage 6: softmax over k + aggregate; agg = val + sum(attn*pe) ----
        {
            float av[16], pv[16];
#pragma unroll
            for (int g = 0; g < 4; g++) {
                float4 v = *(const float4*)&s.kgu[c6][pt6 * 16 + g * 4];
                av[g * 4 + 0] = v.x; av[g * 4 + 1] = v.y;
                av[g * 4 + 2] = v.z; av[g * 4 + 3] = v.w;
                float4 p = *(const float4*)&s.th[c6][pt6 * 16 + g * 4];
                pv[g * 4 + 0] = p.x; pv[g * 4 + 1] = p.y;
                pv[g * 4 + 2] = p.z; pv[g * 4 + 3] = p.w;
            }
            float m = av[0];
#pragma unroll
            for (int k = 1; k < 16; k++) m = fmaxf(m, av[k]);
            float vsum = 0.0f, acc = 0.0f;
#pragma unroll
            for (int k = 0; k < 16; k++) {
                float e = __expf(av[k] - m);
                vsum += e;
                acc = fmaf(e, pv[k], acc);
            }
            g_agg[((size_t)b * NN + n0 + pt6) * CC + c6] = s.vals[pt6][c6] + acc / vsum;
        }
        __syncthreads();
    }
}

// ================= Kernel 4: out = W_end @ agg + b_end + y =================
__global__ __launch_bounds__(256) void k_end(
    const float* __restrict__ y, const float* __restrict__ We_g,
    const float* __restrict__ be_g, float* __restrict__ out)
{
    __shared__ float As[64][65];
    __shared__ float Ws[64][64];
    int b = blockIdx.y, n0 = blockIdx.x * 64, t = threadIdx.x;
#pragma unroll
    for (int i = 0; i < 16; i++) { int e = t + i * 256; Ws[e >> 6][e & 63] = We_g[e]; }
#pragma unroll
    for (int i = 0; i < 16; i++) {
        int e = t + i * 256; int p = e >> 6, c = e & 63;
        As[p][c] = g_agg[((size_t)b * NN + n0 + p) * CC + c];
    }
    __syncthreads();
    int p = t & 63, og = t >> 6;
    float acc[16];
#pragma unroll
    for (int i = 0; i < 16; i++) acc[i] = be_g[og * 16 + i];
#pragma unroll 4
    for (int c = 0; c < 64; c++) {
        float av = As[p][c];
#pragma unroll
        for (int i = 0; i < 16; i++) acc[i] = fmaf(Ws[og * 16 + i][c], av, acc[i]);
    }
#pragma unroll
    for (int i = 0; i < 16; i++) {
        int o = og * 16 + i;
        size_t off = ((size_t)b * CC + o) * NN + n0 + p;
        out[off] = acc[i] + y[off];
    }
}

// ================= launcher =================
extern "C" void kernel_launch(void* const* d_in, const int* in_sizes, int n_in,
                              void* d_out, int out_size)
{
    const float* x       = (const float*)d_in[0];
    const float* y       = (const float*)d_in[1];
    const float* W_start = (const float*)d_in[2];
    const float* b_start = (const float*)d_in[3];
    const float* W_key   = (const float*)d_in[4];
    const float* b_key   = (const float*)d_in[5];
    const float* W_query = (const float*)d_in[6];
    const float* b_query = (const float*)d_in[7];
    const float* P1      = (const float*)d_in[8];
    const float* pb1     = (const float*)d_in[9];
    const float* bn1_g   = (const float*)d_in[10];
    const float* bn1_b   = (const float*)d_in[11];
    const float* bn1_m   = (const float*)d_in[12];
    const float* bn1_v   = (const float*)d_in[13];
    const float* P2      = (const float*)d_in[14];
    const float* pb2     = (const float*)d_in[15];
    const float* A1      = (const float*)d_in[16];
    const float* ab1     = (const float*)d_in[17];
    const float* bn2_g   = (const float*)d_in[18];
    const float* bn2_b   = (const float*)d_in[19];
    const float* bn2_m   = (const float*)d_in[20];
    const float* bn2_v   = (const float*)d_in[21];
    const float* A2      = (const float*)d_in[22];
    const float* ab2     = (const float*)d_in[23];
    const float* W_end   = (const float*)d_in[24];
    const float* b_end   = (const float*)d_in[25];

    cudaFuncSetAttribute(k_attn, cudaFuncAttributeMaxDynamicSharedMemorySize, (int)sizeof(S3));

    k_dummy<<<1, 32>>>();   // slot-shift so ncu -s 5 lands on k_attn
    k_linear_start_key<<<dim3(NN / 64, BB), 256>>>(y, W_start, b_start, W_key, b_key);
    k_knn<<<dim3(NN / 128, BB), 128>>>(x);
    k_attn<<<BB * NN / 8, 256, sizeof(S3)>>>(x, W_query, b_query,
                                             P1, pb1, bn1_g, bn1_b, bn1_m, bn1_v,
                                             P2, pb2, A1, ab1,
                                             bn2_g, bn2_b, bn2_m, bn2_v, A2, ab2);
    k_end<<<dim3(NN / 64, BB), 256>>>(y, W_end, b_end, (float*)d_out);
}

// round 6
// speedup vs baseline: 2.0358x; 1.0606x over previous
#include <cuda_runtime.h>
#include <math.h>

#define BB 4
#define CC 64
#define NN 4096
#define KK 16

// ---------------- scratch (no allocations allowed) ----------------
__device__ float g_val_t[BB * NN * CC];   // y1 (value), layout (B,N,C)
__device__ float g_key_t[BB * NN * CC];   // key, layout (B,N,C)
__device__ float g_agg[BB * NN * CC];     // aggregated features, layout (B,N,C)
__device__ int   g_idx[BB * NN * KK];     // knn indices

__device__ __forceinline__ void fma4(float4& a, float w, const float4 v) {
    a.x = fmaf(w, v.x, a.x);
    a.y = fmaf(w, v.y, a.y);
    a.z = fmaf(w, v.z, a.z);
    a.w = fmaf(w, v.w, a.w);
}

// ================= dummy kernel (shifts ncu -s 5 capture slot onto k_attn) =================
__global__ void k_dummy() {}

// ================= Kernel 1: y1 = W_start@y+b ; key = W_key@y1+b (written transposed (B,N,C)) =================
__global__ __launch_bounds__(256) void k_linear_start_key(
    const float* __restrict__ y,
    const float* __restrict__ Ws_g, const float* __restrict__ bs_g,
    const float* __restrict__ Wk_g, const float* __restrict__ bk_g)
{
    __shared__ float ys[64][64];
    __shared__ float y1s[64][64];
    __shared__ float Ws[64][64];
    int b = blockIdx.y, n0 = blockIdx.x * 64, t = threadIdx.x;

#pragma unroll
    for (int i = 0; i < 16; i++) { int e = t + i * 256; Ws[e >> 6][e & 63] = Ws_g[e]; }
#pragma unroll
    for (int i = 0; i < 16; i++) {
        int e = t + i * 256; int c = e >> 6, p = e & 63;
        ys[c][p] = y[((size_t)b * CC + c) * NN + n0 + p];
    }
    __syncthreads();

    int p = t & 63, og = t >> 6;
    float acc[16];
#pragma unroll
    for (int i = 0; i < 16; i++) acc[i] = bs_g[og * 16 + i];
#pragma unroll 4
    for (int c = 0; c < 64; c++) {
        float yv = ys[c][p];
#pragma unroll
        for (int i = 0; i < 16; i++) acc[i] = fmaf(Ws[og * 16 + i][c], yv, acc[i]);
    }
#pragma unroll
    for (int i = 0; i < 16; i++) y1s[og * 16 + i][p] = acc[i];
    {
        float4* vo = (float4*)&g_val_t[(((size_t)b * NN) + n0 + p) * CC + og * 16];
        vo[0] = make_float4(acc[0], acc[1], acc[2], acc[3]);
        vo[1] = make_float4(acc[4], acc[5], acc[6], acc[7]);
        vo[2] = make_float4(acc[8], acc[9], acc[10], acc[11]);
        vo[3] = make_float4(acc[12], acc[13], acc[14], acc[15]);
    }
    __syncthreads();
#pragma unroll
    for (int i = 0; i < 16; i++) { int e = t + i * 256; Ws[e >> 6][e & 63] = Wk_g[e]; }
    __syncthreads();
#pragma unroll
    for (int i = 0; i < 16; i++) acc[i] = bk_g[og * 16 + i];
#pragma unroll 4
    for (int c = 0; c < 64; c++) {
        float yv = y1s[c][p];
#pragma unroll
        for (int i = 0; i < 16; i++) acc[i] = fmaf(Ws[og * 16 + i][c], yv, acc[i]);
    }
    {
        float4* ko = (float4*)&g_key_t[(((size_t)b * NN) + n0 + p) * CC + og * 16];
        ko[0] = make_float4(acc[0], acc[1], acc[2], acc[3]);
        ko[1] = make_float4(acc[4], acc[5], acc[6], acc[7]);
        ko[2] = make_float4(acc[8], acc[9], acc[10], acc[11]);
        ko[3] = make_float4(acc[12], acc[13], acc[14], acc[15]);
    }
}

// ================= Kernel 2: KNN (top-16 nearest incl. self) =================
// 64 queries/block -> grid = 256 >= 148 (avoids low-grid issue throttle); small body.
__global__ __launch_bounds__(64) void k_knn(const float* __restrict__ x)
{
    __shared__ float sxs[64], sys[64], szs[64], ssq[64];
    int b = blockIdx.y;
    int i = blockIdx.x * 64 + threadIdx.x;
    const float* xb = x + (size_t)b * 3 * NN;
    float qx = xb[i], qy = xb[NN + i], qz = xb[2 * NN + i];
    float qsq = qx * qx + qy * qy + qz * qz;

    float bd[16]; int bi[16];
#pragma unroll
    for (int s = 0; s < 16; s++) { bd[s] = 3.0e38f; bi[s] = 0; }

    for (int c0 = 0; c0 < NN; c0 += 64) {
        int j = c0 + threadIdx.x;
        float a0 = xb[j], a1 = xb[NN + j], a2 = xb[2 * NN + j];
        sxs[threadIdx.x] = a0; sys[threadIdx.x] = a1; szs[threadIdx.x] = a2;
        ssq[threadIdx.x] = a0 * a0 + a1 * a1 + a2 * a2;
        __syncthreads();
        for (int jj = 0; jj < 64; jj++) {
            float dot = qx * sxs[jj] + qy * sys[jj] + qz * szs[jj];
            float d = qsq - 2.0f * dot + ssq[jj];
            if (d < bd[15]) {
                bd[15] = d; bi[15] = c0 + jj;
#pragma unroll
                for (int s = 15; s > 0; --s) {
                    if (bd[s] < bd[s - 1]) {
                        float td = bd[s]; bd[s] = bd[s - 1]; bd[s - 1] = td;
                        int ti = bi[s]; bi[s] = bi[s - 1]; bi[s - 1] = ti;
                    } else break;
                }
            }
        }
        __syncthreads();
    }
#pragma unroll
    for (int s = 0; s < 16; s++) g_idx[((size_t)b * NN + i) * KK + s] = bi[s];
}

// ================= Kernel 3: fused attention, persistent blocks, 4 points/tile =================
struct __align__(16) S3 {
    float A1s[64][260];     // [c][a], BN-folded A1 (260 = 4*65: float4-aligned rows)
    float A2s[256][68];     // [h][c]
    float P2s[64][68];      // [h][c]
    float h1s[128][68];     // one h-half of h1
    float th[64][68];       // P1-hidden [h][e] -> pe [c][e]
    float kgu[64][68];      // key [c][e] -> u [c][e] -> logits [c][e]
    float P1p[64][3];
    float Wq[64][3];
    float b1p[256];
    float s2s[256];
    float s1s[64];
    float pb1p[64];
    float pb2s[64];
    float ab2s[64];
    float bqs[64];
    float posr[4][3][16];
    float qy[4][64];
    float vals[4][64];
};

#define NTILES (BB * NN / 4)   // 4096 tiles of 4 points

__global__ void __launch_bounds__(256, 1) k_attn(
    const float* __restrict__ x,
    const float* __restrict__ Wq_g, const float* __restrict__ bq_g,
    const float* __restrict__ P1, const float* __restrict__ pb1,
    const float* __restrict__ bn1_g, const float* __restrict__ bn1_b,
    const float* __restrict__ bn1_m, const float* __restrict__ bn1_v,
    const float* __restrict__ P2, const float* __restrict__ pb2,
    const float* __restrict__ A1, const float* __restrict__ ab1,
    const float* __restrict__ bn2_g, const float* __restrict__ bn2_b,
    const float* __restrict__ bn2_m, const float* __restrict__ bn2_v,
    const float* __restrict__ A2, const float* __restrict__ ab2)
{
    extern __shared__ char smraw[];
    S3& s = *(S3*)smraw;
    int t = threadIdx.x;

    // ---- fold BN into weights/biases, stage weights to smem (ONCE per block) ----
    {
        float s2 = bn2_g[t] / sqrtf(bn2_v[t] + 1e-5f);
        s.s2s[t] = s2;
        s.b1p[t] = (ab1[t] - bn2_m[t]) * s2 + bn2_b[t];
    }
    if (t < 64) {
        float s1 = bn1_g[t] / sqrtf(bn1_v[t] + 1e-5f);
        s.s1s[t] = s1;
        s.pb1p[t] = (pb1[t] - bn1_m[t]) * s1 + bn1_b[t];
        s.pb2s[t] = pb2[t];
        s.ab2s[t] = ab2[t];
        s.bqs[t] = bq_g[t];
    }
    if (t < 192) s.Wq[t / 3][t % 3] = Wq_g[t];
    __syncthreads();
    if (t < 192) s.P1p[t / 3][t % 3] = P1[t] * s.s1s[t / 3];
#pragma unroll
    for (int i = 0; i < 64; i++) {
        int e = t + i * 256; int a = e >> 6, c = e & 63;
        s.A1s[c][a] = A1[e] * s.s2s[a];
    }
#pragma unroll
    for (int i = 0; i < 64; i++) {
        int e = t + i * 256; int c = e >> 8, h = e & 255;
        s.A2s[h][c] = A2[e];
    }
#pragma unroll
    for (int i = 0; i < 16; i++) {
        int e = t + i * 256; int c = e >> 6, h = e & 63;
        s.P2s[h][c] = P2[e];
    }
    __syncthreads();

    // per-thread stage identities
    const int cg2 = t >> 4, eg2 = t & 15;         // stage 2/5: 4c x 4e tile
    const int c20 = cg2 * 4, e20 = eg2 * 4;
    const int ag = t >> 3, eg4 = t & 7;           // stage 4: 4a x 8e tile
    const int a0r = ag * 4, e40 = eg4 * 8;
    const int pt6 = t >> 6, c6 = t & 63;          // stage 0b/6: (pt, c)

    // ---- persistent tile loop: one 4-point tile per iteration ----
    for (int tile = blockIdx.x; tile < NTILES; tile += gridDim.x) {
        int b = tile >> 10;                  // 1024 tiles per batch
        int n0 = (tile & 1023) * 4;
        const float* xb = x + (size_t)b * 3 * NN;
        const int* idxb = &g_idx[(size_t)b * NN * KK];

        // ---- stage 0: key gather (kgu <- key), posr, qy, vals ----
        {
            int e = t & 63, cq = t >> 6;
            int pt = e >> 4, k = e & 15;
            int j = idxb[(n0 + pt) * KK + k];
            const float4* kp = (const float4*)&g_key_t[((size_t)b * NN + j) * CC + cq * 16];
            float4 v0 = kp[0], v1 = kp[1], v2 = kp[2], v3 = kp[3];
            int cb = cq * 16;
            s.kgu[cb + 0][e] = v0.x;  s.kgu[cb + 1][e] = v0.y;
            s.kgu[cb + 2][e] = v0.z;  s.kgu[cb + 3][e] = v0.w;
            s.kgu[cb + 4][e] = v1.x;  s.kgu[cb + 5][e] = v1.y;
            s.kgu[cb + 6][e] = v1.z;  s.kgu[cb + 7][e] = v1.w;
            s.kgu[cb + 8][e] = v2.x;  s.kgu[cb + 9][e] = v2.y;
            s.kgu[cb + 10][e] = v2.z; s.kgu[cb + 11][e] = v2.w;
            s.kgu[cb + 12][e] = v3.x; s.kgu[cb + 13][e] = v3.y;
            s.kgu[cb + 14][e] = v3.z; s.kgu[cb + 15][e] = v3.w;
        }
        if (t < 192) {
            int pt = t / 48, r = t % 48, d = r >> 4, k = r & 15;
            int j = idxb[(n0 + pt) * KK + k];
            s.posr[pt][d][k] = xb[d * NN + n0 + pt] - xb[d * NN + j];
        }
        {
            int n = n0 + pt6;
            s.qy[pt6][c6] = s.bqs[c6] + s.Wq[c6][0] * xb[n] + s.Wq[c6][1] * xb[NN + n]
                          + s.Wq[c6][2] * xb[2 * NN + n];
            s.vals[pt6][c6] = g_val_t[((size_t)b * NN + n) * CC + c6];
        }
        __syncthreads();

        // ---- stage 1: th[h][e] = relu(P1'@pos_rel + pb1') ----
        {
            int h = t & 63, pt = t >> 6;
            float p0 = s.P1p[h][0], p1 = s.P1p[h][1], p2 = s.P1p[h][2], bb = s.pb1p[h];
#pragma unroll
            for (int g = 0; g < 4; g++) {
                float4 o;
                float* ov = (float*)&o;
#pragma unroll
                for (int kk = 0; kk < 4; kk++) {
                    int k = g * 4 + kk;
                    float a = bb + p0 * s.posr[pt][0][k] + p1 * s.posr[pt][1][k]
                                 + p2 * s.posr[pt][2][k];
                    ov[kk] = fmaxf(a, 0.0f);
                }
                *(float4*)&s.th[h][pt * 16 + g * 4] = o;
            }
        }
        __syncthreads();

        // ---- stage 2: pe = P2@th + pb2 (4c x 4e per-thread tile, all-unique LDS) ----
        float4 pa0, pa1, pa2, pa3;
        {
            float b0 = s.pb2s[c20], b1 = s.pb2s[c20 + 1], b2 = s.pb2s[c20 + 2], b3 = s.pb2s[c20 + 3];
            pa0 = make_float4(b0, b0, b0, b0);
            pa1 = make_float4(b1, b1, b1, b1);
            pa2 = make_float4(b2, b2, b2, b2);
            pa3 = make_float4(b3, b3, b3, b3);
#pragma unroll 4
            for (int h = 0; h < 64; h++) {
                float4 w = *(const float4*)&s.P2s[h][c20];
                float4 tv = *(const float4*)&s.th[h][e20];
                fma4(pa0, w.x, tv); fma4(pa1, w.y, tv);
                fma4(pa2, w.z, tv); fma4(pa3, w.w, tv);
            }
        }
        __syncthreads();   // all reads of th (hidden) complete
        // ---- stage 2b: th <- pe ; kgu <- u = (q - key) + pe ----
        {
            int pt = e20 >> 4;
            float q0 = s.qy[pt][c20], q1 = s.qy[pt][c20 + 1];
            float q2 = s.qy[pt][c20 + 2], q3 = s.qy[pt][c20 + 3];
            float4 k0 = *(const float4*)&s.kgu[c20][e20];
            float4 k1 = *(const float4*)&s.kgu[c20 + 1][e20];
            float4 k2 = *(const float4*)&s.kgu[c20 + 2][e20];
            float4 k3 = *(const float4*)&s.kgu[c20 + 3][e20];
            *(float4*)&s.th[c20][e20] = pa0;
            *(float4*)&s.th[c20 + 1][e20] = pa1;
            *(float4*)&s.th[c20 + 2][e20] = pa2;
            *(float4*)&s.th[c20 + 3][e20] = pa3;
            float4 u;
            u.x = (q0 - k0.x) + pa0.x; u.y = (q0 - k0.y) + pa0.y;
            u.z = (q0 - k0.z) + pa0.z; u.w = (q0 - k0.w) + pa0.w;
            *(float4*)&s.kgu[c20][e20] = u;
            u.x = (q1 - k1.x) + pa1.x; u.y = (q1 - k1.y) + pa1.y;
            u.z = (q1 - k1.z) + pa1.z; u.w = (q1 - k1.w) + pa1.w;
            *(float4*)&s.kgu[c20 + 1][e20] = u;
            u.x = (q2 - k2.x) + pa2.x; u.y = (q2 - k2.y) + pa2.y;
            u.z = (q2 - k2.z) + pa2.z; u.w = (q2 - k2.w) + pa2.w;
            *(float4*)&s.kgu[c20 + 2][e20] = u;
            u.x = (q3 - k3.x) + pa3.x; u.y = (q3 - k3.y) + pa3.y;
            u.z = (q3 - k3.z) + pa3.z; u.w = (q3 - k3.w) + pa3.w;
            *(float4*)&s.kgu[c20 + 3][e20] = u;
        }
        __syncthreads();

        // ---- stages 4+5 over two h-halves; stage-5 accumulators persist in regs ----
        float4 L0, L1, L2, L3;
        {
            float b0 = s.ab2s[c20], b1 = s.ab2s[c20 + 1], b2 = s.ab2s[c20 + 2], b3 = s.ab2s[c20 + 3];
            L0 = make_float4(b0, b0, b0, b0);
            L1 = make_float4(b1, b1, b1, b1);
            L2 = make_float4(b2, b2, b2, b2);
            L3 = make_float4(b3, b3, b3, b3);
        }
#pragma unroll
        for (int r = 0; r < 2; r++) {
            // stage 4: h1[half] = relu(A1'@u + b1')  (4a x 8e tile)
            {
                int abase = r * 128 + a0r;
                float b0 = s.b1p[abase], b1 = s.b1p[abase + 1];
                float b2 = s.b1p[abase + 2], b3 = s.b1p[abase + 3];
                float4 A00 = make_float4(b0, b0, b0, b0), A01 = A00;
                float4 A10 = make_float4(b1, b1, b1, b1), A11 = A10;
                float4 A20 = make_float4(b2, b2, b2, b2), A21 = A20;
                float4 A30 = make_float4(b3, b3, b3, b3), A31 = A30;
#pragma unroll 4
                for (int c = 0; c < 64; c++) {
                    float4 w = *(const float4*)&s.A1s[c][abase];
                    float4 u0 = *(const float4*)&s.kgu[c][e40];
                    float4 u1 = *(const float4*)&s.kgu[c][e40 + 4];
                    fma4(A00, w.x, u0); fma4(A01, w.x, u1);
                    fma4(A10, w.y, u0); fma4(A11, w.y, u1);
                    fma4(A20, w.z, u0); fma4(A21, w.z, u1);
                    fma4(A30, w.w, u0); fma4(A31, w.w, u1);
                }
#define RELU4(v) v.x = fmaxf(v.x, 0.f); v.y = fmaxf(v.y, 0.f); v.z = fmaxf(v.z, 0.f); v.w = fmaxf(v.w, 0.f);
                RELU4(A00) RELU4(A01) RELU4(A10) RELU4(A11)
                RELU4(A20) RELU4(A21) RELU4(A30) RELU4(A31)
#undef RELU4
                *(float4*)&s.h1s[a0r][e40] = A00;     *(float4*)&s.h1s[a0r][e40 + 4] = A01;
                *(float4*)&s.h1s[a0r + 1][e40] = A10; *(float4*)&s.h1s[a0r + 1][e40 + 4] = A11;
                *(float4*)&s.h1s[a0r + 2][e40] = A20; *(float4*)&s.h1s[a0r + 2][e40 + 4] = A21;
                *(float4*)&s.h1s[a0r + 3][e40] = A30; *(float4*)&s.h1s[a0r + 3][e40 + 4] = A31;
            }
            __syncthreads();
            // stage 5 partial: logits += A2[:, half]@h1[half]  (4c x 4e tile)
#pragma unroll 4
            for (int j = 0; j < 128; j++) {
                float4 w = *(const float4*)&s.A2s[r * 128 + j][c20];
                float4 hv = *(const float4*)&s.h1s[j][e20];
                fma4(L0, w.x, hv); fma4(L1, w.y, hv);
                fma4(L2, w.z, hv); fma4(L3, w.w, hv);
            }
            __syncthreads();   // h1 reads done before overwrite (r=0) / before logit write (r=1)
        }
        // write logits into kgu (u is dead)
        *(float4*)&s.kgu[c20][e20] = L0;
        *(float4*)&s.kgu[c20 + 1][e20] = L1;
        *(float4*)&s.kgu[c20 + 2][e20] = L2;
        *(float4*)&s.kgu[c20 + 3][e20] = L3;
        __syncthreads();

        // ---- stage 6: softmax over k + aggregate; agg = val + sum(attn*pe) ----
        {
            float av[16], pv[16];
#pragma unroll
            for (int g = 0; g < 4; g++) {
                float4 v = *(const float4*)&s.kgu[c6][pt6 * 16 + g * 4];
                av[g * 4 + 0] = v.x; av[g * 4 + 1] = v.y;
                av[g * 4 + 2] = v.z; av[g * 4 + 3] = v.w;
                float4 p = *(const float4*)&s.th[c6][pt6 * 16 + g * 4];
                pv[g * 4 + 0] = p.x; pv[g * 4 + 1] = p.y;
                pv[g * 4 + 2] = p.z; pv[g * 4 + 3] = p.w;
            }
            float m = av[0];
#pragma unroll
            for (int k = 1; k < 16; k++) m = fmaxf(m, av[k]);
            float vsum = 0.0f, acc = 0.0f;
#pragma unroll
            for (int k = 0; k < 16; k++) {
                float e = __expf(av[k] - m);
                vsum += e;
                acc = fmaf(e, pv[k], acc);
            }
            g_agg[((size_t)b * NN + n0 + pt6) * CC + c6] = s.vals[pt6][c6] + acc / vsum;
        }
        __syncthreads();
    }
}

// ================= Kernel 4: out = W_end @ agg + b_end + y =================
__global__ __launch_bounds__(256) void k_end(
    const float* __restrict__ y, const float* __restrict__ We_g,
    const float* __restrict__ be_g, float* __restrict__ out)
{
    __shared__ float As[64][65];
    __shared__ float Ws[64][64];
    int b = blockIdx.y, n0 = blockIdx.x * 64, t = threadIdx.x;
#pragma unroll
    for (int i = 0; i < 16; i++) { int e = t + i * 256; Ws[e >> 6][e & 63] = We_g[e]; }
#pragma unroll
    for (int i = 0; i < 16; i++) {
        int e = t + i * 256; int p = e >> 6, c = e & 63;
        As[p][c] = g_agg[((size_t)b * NN + n0 + p) * CC + c];
    }
    __syncthreads();
    int p = t & 63, og = t >> 6;
    float acc[16];
#pragma unroll
    for (int i = 0; i < 16; i++) acc[i] = be_g[og * 16 + i];
#pragma unroll 4
    for (int c = 0; c < 64; c++) {
        float av = As[p][c];
#pragma unroll
        for (int i = 0; i < 16; i++) acc[i] = fmaf(Ws[og * 16 + i][c], av, acc[i]);
    }
#pragma unroll
    for (int i = 0; i < 16; i++) {
        int o = og * 16 + i;
        size_t off = ((size_t)b * CC + o) * NN + n0 + p;
        out[off] = acc[i] + y[off];
    }
}

// ================= launcher =================
extern "C" void kernel_launch(void* const* d_in, const int* in_sizes, int n_in,
                              void* d_out, int out_size)
{
    const float* x       = (const float*)d_in[0];
    const float* y       = (const float*)d_in[1];
    const float* W_start = (const float*)d_in[2];
    const float* b_start = (const float*)d_in[3];
    const float* W_key   = (const float*)d_in[4];
    const float* b_key   = (const float*)d_in[5];
    const float* W_query = (const float*)d_in[6];
    const float* b_query = (const float*)d_in[7];
    const float* P1      = (const float*)d_in[8];
    const float* pb1     = (const float*)d_in[9];
    const float* bn1_g   = (const float*)d_in[10];
    const float* bn1_b   = (const float*)d_in[11];
    const float* bn1_m   = (const float*)d_in[12];
    const float* bn1_v   = (const float*)d_in[13];
    const float* P2      = (const float*)d_in[14];
    const float* pb2     = (const float*)d_in[15];
    const float* A1      = (const float*)d_in[16];
    const float* ab1     = (const float*)d_in[17];
    const float* bn2_g   = (const float*)d_in[18];
    const float* bn2_b   = (const float*)d_in[19];
    const float* bn2_m   = (const float*)d_in[20];
    const float* bn2_v   = (const float*)d_in[21];
    const float* A2      = (const float*)d_in[22];
    const float* ab2     = (const float*)d_in[23];
    const float* W_end   = (const float*)d_in[24];
    const float* b_end   = (const float*)d_in[25];

    cudaFuncSetAttribute(k_attn, cudaFuncAttributeMaxDynamicSharedMemorySize, (int)sizeof(S3));

    k_dummy<<<1, 32>>>();   // slot-shift so ncu -s 5 lands on k_attn
    k_linear_start_key<<<dim3(NN / 64, BB), 256>>>(y, W_start, b_start, W_key, b_key);
    k_knn<<<dim3(NN / 64, BB), 64>>>(x);
    k_attn<<<148, 256, sizeof(S3)>>>(x, W_query, b_query,
                                     P1, pb1, bn1_g, bn1_b, bn1_m, bn1_v,
                                     P2, pb2, A1, ab1,
                                     bn2_g, bn2_b, bn2_m, bn2_v, A2, ab2);
    k_end<<<dim3(NN / 64, BB), 256>>>(y, W_end, b_end, (float*)d_out);
}

// round 7
// speedup vs baseline: 2.0434x; 1.0038x over previous
#include <cuda_runtime.h>
#include <math.h>

#define BB 4
#define CC 64
#define NN 4096
#define KK 16
#define NSPL 2

// ---------------- scratch (no allocations allowed) ----------------
__device__ float g_val_t[BB * NN * CC];   // y1 (value), layout (B,N,C)
__device__ float g_key_t[BB * NN * CC];   // key, layout (B,N,C)
__device__ float g_agg[BB * NN * CC];     // aggregated features, layout (B,N,C)
__device__ int   g_idx[BB * NN * KK];     // knn indices (final)
__device__ float g_knn_d[BB][NSPL][NN][KK];
__device__ int   g_knn_i[BB][NSPL][NN][KK];

__device__ __forceinline__ void fma4(float4& a, float w, const float4 v) {
    a.x = fmaf(w, v.x, a.x);
    a.y = fmaf(w, v.y, a.y);
    a.z = fmaf(w, v.z, a.z);
    a.w = fmaf(w, v.w, a.w);
}

// ================= dummy kernel (ncu slot alignment) =================
__global__ void k_dummy() {}

// ================= Kernel 1: y1 = W_start@y+b ; key = W_key@y1+b (written transposed (B,N,C)) =================
__global__ __launch_bounds__(256) void k_linear_start_key(
    const float* __restrict__ y,
    const float* __restrict__ Ws_g, const float* __restrict__ bs_g,
    const float* __restrict__ Wk_g, const float* __restrict__ bk_g)
{
    __shared__ float ys[64][64];
    __shared__ float y1s[64][64];
    __shared__ float Ws[64][64];
    int b = blockIdx.y, n0 = blockIdx.x * 64, t = threadIdx.x;

#pragma unroll
    for (int i = 0; i < 16; i++) { int e = t + i * 256; Ws[e >> 6][e & 63] = Ws_g[e]; }
#pragma unroll
    for (int i = 0; i < 16; i++) {
        int e = t + i * 256; int c = e >> 6, p = e & 63;
        ys[c][p] = y[((size_t)b * CC + c) * NN + n0 + p];
    }
    __syncthreads();

    int p = t & 63, og = t >> 6;
    float acc[16];
#pragma unroll
    for (int i = 0; i < 16; i++) acc[i] = bs_g[og * 16 + i];
#pragma unroll 4
    for (int c = 0; c < 64; c++) {
        float yv = ys[c][p];
#pragma unroll
        for (int i = 0; i < 16; i++) acc[i] = fmaf(Ws[og * 16 + i][c], yv, acc[i]);
    }
#pragma unroll
    for (int i = 0; i < 16; i++) y1s[og * 16 + i][p] = acc[i];
    {
        float4* vo = (float4*)&g_val_t[(((size_t)b * NN) + n0 + p) * CC + og * 16];
        vo[0] = make_float4(acc[0], acc[1], acc[2], acc[3]);
        vo[1] = make_float4(acc[4], acc[5], acc[6], acc[7]);
        vo[2] = make_float4(acc[8], acc[9], acc[10], acc[11]);
        vo[3] = make_float4(acc[12], acc[13], acc[14], acc[15]);
    }
    __syncthreads();
#pragma unroll
    for (int i = 0; i < 16; i++) { int e = t + i * 256; Ws[e >> 6][e & 63] = Wk_g[e]; }
    __syncthreads();
#pragma unroll
    for (int i = 0; i < 16; i++) acc[i] = bk_g[og * 16 + i];
#pragma unroll 4
    for (int c = 0; c < 64; c++) {
        float yv = y1s[c][p];
#pragma unroll
        for (int i = 0; i < 16; i++) acc[i] = fmaf(Ws[og * 16 + i][c], yv, acc[i]);
    }
    {
        float4* ko = (float4*)&g_key_t[(((size_t)b * NN) + n0 + p) * CC + og * 16];
        ko[0] = make_float4(acc[0], acc[1], acc[2], acc[3]);
        ko[1] = make_float4(acc[4], acc[5], acc[6], acc[7]);
        ko[2] = make_float4(acc[8], acc[9], acc[10], acc[11]);
        ko[3] = make_float4(acc[12], acc[13], acc[14], acc[15]);
    }
}

// ================= Kernel 2a: KNN partial (candidate-split, d' = ssq - 2*dot ordering) =================
__global__ __launch_bounds__(64) void k_knn_part(const float* __restrict__ x)
{
    __shared__ float4 cand[64];
    int b = blockIdx.z, sp = blockIdx.y;
    int i = blockIdx.x * 64 + threadIdx.x;
    const float* xb = x + (size_t)b * 3 * NN;
    float qx = xb[i], qy = xb[NN + i], qz = xb[2 * NN + i];

    float bd[16]; int bi[16];
#pragma unroll
    for (int s = 0; s < 16; s++) { bd[s] = 3.0e38f; bi[s] = 0; }

    int base = sp * (NN / NSPL);
    for (int c0 = 0; c0 < NN / NSPL; c0 += 64) {
        int j = base + c0 + threadIdx.x;
        float ax = xb[j], ay = xb[NN + j], az = xb[2 * NN + j];
        cand[threadIdx.x] = make_float4(ax, ay, az, ax * ax + ay * ay + az * az);
        __syncthreads();
        for (int jj = 0; jj < 64; jj++) {
            float4 cv = cand[jj];
            float dot = qx * cv.x + qy * cv.y + qz * cv.z;
            float d = fmaf(-2.0f, dot, cv.w);
            if (d < bd[15]) {
                bd[15] = d; bi[15] = base + c0 + jj;
#pragma unroll
                for (int s = 15; s > 0; --s) {
                    if (bd[s] < bd[s - 1]) {
                        float td = bd[s]; bd[s] = bd[s - 1]; bd[s - 1] = td;
                        int ti = bi[s]; bi[s] = bi[s - 1]; bi[s - 1] = ti;
                    } else break;
                }
            }
        }
        __syncthreads();
    }
#pragma unroll
    for (int s = 0; s < 16; s++) { g_knn_d[b][sp][i][s] = bd[s]; g_knn_i[b][sp][i][s] = bi[s]; }
}

// ================= Kernel 2b: merge the NSPL sorted partial lists =================
__global__ __launch_bounds__(128) void k_knn_merge()
{
    int g = blockIdx.x * 128 + threadIdx.x;
    int b = g >> 12, n = g & (NN - 1);
    float bd[16]; int bi[16];
#pragma unroll
    for (int s = 0; s < 16; s++) { bd[s] = g_knn_d[b][0][n][s]; bi[s] = g_knn_i[b][0][n][s]; }
    for (int s = 0; s < 16; s++) {
        float d = g_knn_d[b][1][n][s];
        if (d >= bd[15]) break;     // sorted ascending
        bd[15] = d; bi[15] = g_knn_i[b][1][n][s];
#pragma unroll
        for (int u = 15; u > 0; --u) {
            if (bd[u] < bd[u - 1]) {
                float td = bd[u]; bd[u] = bd[u - 1]; bd[u - 1] = td;
                int ti = bi[u]; bi[u] = bi[u - 1]; bi[u - 1] = ti;
            } else break;
        }
    }
#pragma unroll
    for (int s = 0; s < 16; s++) g_idx[((size_t)b * NN + n) * KK + s] = bi[s];
}

// ================= Kernel 3: fused attention, persistent blocks, register epilogue =================
struct __align__(16) S3 {
    float A1s[64][260];     // [c][a], BN-folded A1
    float A2s[256][68];     // [h][c]
    float P2s[64][68];      // [h][c]
    float h1s[128][68];     // one h-half of h1
    float th[64][68];       // P1-hidden [h][e]
    float kgu[64][68];      // key [c][e] -> u [c][e]
    float P1p[64][3];
    float Wq[64][3];
    float b1p[256];
    float s2s[256];
    float s1s[64];
    float pb1p[64];
    float pb2s[64];
    float ab2s[64];
    float bqs[64];
    float posr[4][3][16];
    float qy[4][64];
    float vals[4][64];
};

#define NTILES (BB * NN / 4)   // 4096 tiles of 4 points

__global__ void __launch_bounds__(256, 1) k_attn(
    const float* __restrict__ x,
    const float* __restrict__ Wq_g, const float* __restrict__ bq_g,
    const float* __restrict__ P1, const float* __restrict__ pb1,
    const float* __restrict__ bn1_g, const float* __restrict__ bn1_b,
    const float* __restrict__ bn1_m, const float* __restrict__ bn1_v,
    const float* __restrict__ P2, const float* __restrict__ pb2,
    const float* __restrict__ A1, const float* __restrict__ ab1,
    const float* __restrict__ bn2_g, const float* __restrict__ bn2_b,
    const float* __restrict__ bn2_m, const float* __restrict__ bn2_v,
    const float* __restrict__ A2, const float* __restrict__ ab2)
{
    extern __shared__ char smraw[];
    S3& s = *(S3*)smraw;
    int t = threadIdx.x;

    // ---- fold BN into weights/biases (once per persistent block) ----
    {
        float s2 = bn2_g[t] / sqrtf(bn2_v[t] + 1e-5f);
        s.s2s[t] = s2;
        s.b1p[t] = (ab1[t] - bn2_m[t]) * s2 + bn2_b[t];
    }
    if (t < 64) {
        float s1 = bn1_g[t] / sqrtf(bn1_v[t] + 1e-5f);
        s.s1s[t] = s1;
        s.pb1p[t] = (pb1[t] - bn1_m[t]) * s1 + bn1_b[t];
        s.pb2s[t] = pb2[t];
        s.ab2s[t] = ab2[t];
        s.bqs[t] = bq_g[t];
    }
    if (t < 192) s.Wq[t / 3][t % 3] = Wq_g[t];
    __syncthreads();
    if (t < 192) s.P1p[t / 3][t % 3] = P1[t] * s.s1s[t / 3];
#pragma unroll
    for (int i = 0; i < 64; i++) {
        int e = t + i * 256; int a = e >> 6, c = e & 63;
        s.A1s[c][a] = A1[e] * s.s2s[a];
    }
#pragma unroll
    for (int i = 0; i < 64; i++) {
        int e = t + i * 256; int c = e >> 8, h = e & 255;
        s.A2s[h][c] = A2[e];
    }
#pragma unroll
    for (int i = 0; i < 16; i++) {
        int e = t + i * 256; int c = e >> 6, h = e & 63;
        s.P2s[h][c] = P2[e];
    }
    __syncthreads();

    // per-thread stage identities
    const int cg2 = t >> 4, eg2 = t & 15;         // stage 2/5: 4c x 4e tile
    const int c20 = cg2 * 4, e20 = eg2 * 4;
    const int ag = t >> 3, eg4 = t & 7;           // stage 4: 4a x 8e tile
    const int a0r = ag * 4, e40 = eg4 * 8;
    const int pt6 = t >> 6, c6 = t & 63;          // stage 0b: (pt, c)
    const int ptE = e20 >> 4;                     // epilogue point

    for (int tile = blockIdx.x; tile < NTILES; tile += gridDim.x) {
        int b = tile >> 10;
        int n0 = (tile & 1023) * 4;
        const float* xb = x + (size_t)b * 3 * NN;
        const int* idxb = &g_idx[(size_t)b * NN * KK];

        // ---- stage 0: key gather (kgu <- key), posr, qy, vals ----
        {
            int e = t & 63, cq = t >> 6;
            int pt = e >> 4, k = e & 15;
            int j = idxb[(n0 + pt) * KK + k];
            const float4* kp = (const float4*)&g_key_t[((size_t)b * NN + j) * CC + cq * 16];
            float4 v0 = kp[0], v1 = kp[1], v2 = kp[2], v3 = kp[3];
            int cb = cq * 16;
            s.kgu[cb + 0][e] = v0.x;  s.kgu[cb + 1][e] = v0.y;
            s.kgu[cb + 2][e] = v0.z;  s.kgu[cb + 3][e] = v0.w;
            s.kgu[cb + 4][e] = v1.x;  s.kgu[cb + 5][e] = v1.y;
            s.kgu[cb + 6][e] = v1.z;  s.kgu[cb + 7][e] = v1.w;
            s.kgu[cb + 8][e] = v2.x;  s.kgu[cb + 9][e] = v2.y;
            s.kgu[cb + 10][e] = v2.z; s.kgu[cb + 11][e] = v2.w;
            s.kgu[cb + 12][e] = v3.x; s.kgu[cb + 13][e] = v3.y;
            s.kgu[cb + 14][e] = v3.z; s.kgu[cb + 15][e] = v3.w;
        }
        if (t < 192) {
            int pt = t / 48, r = t % 48, d = r >> 4, k = r & 15;
            int j = idxb[(n0 + pt) * KK + k];
            s.posr[pt][d][k] = xb[d * NN + n0 + pt] - xb[d * NN + j];
        }
        {
            int n = n0 + pt6;
            s.qy[pt6][c6] = s.bqs[c6] + s.Wq[c6][0] * xb[n] + s.Wq[c6][1] * xb[NN + n]
                          + s.Wq[c6][2] * xb[2 * NN + n];
            s.vals[pt6][c6] = g_val_t[((size_t)b * NN + n) * CC + c6];
        }
        __syncthreads();   // sync0

        // ---- stage 1: th[h][e] = relu(P1'@pos_rel + pb1') ----
        {
            int h = t & 63, pt = t >> 6;
            float p0 = s.P1p[h][0], p1 = s.P1p[h][1], p2 = s.P1p[h][2], bb = s.pb1p[h];
#pragma unroll
            for (int g = 0; g < 4; g++) {
                float4 o;
                float* ov = (float*)&o;
#pragma unroll
                for (int kk = 0; kk < 4; kk++) {
                    int k = g * 4 + kk;
                    float a = bb + p0 * s.posr[pt][0][k] + p1 * s.posr[pt][1][k]
                                 + p2 * s.posr[pt][2][k];
                    ov[kk] = fmaxf(a, 0.0f);
                }
                *(float4*)&s.th[h][pt * 16 + g * 4] = o;
            }
        }
        __syncthreads();   // sync1

        // ---- stage 2: pe = P2@th + pb2 (kept in registers pa0..3) ----
        float4 pa0, pa1, pa2, pa3;
        {
            float b0 = s.pb2s[c20], b1 = s.pb2s[c20 + 1], b2 = s.pb2s[c20 + 2], b3 = s.pb2s[c20 + 3];
            pa0 = make_float4(b0, b0, b0, b0);
            pa1 = make_float4(b1, b1, b1, b1);
            pa2 = make_float4(b2, b2, b2, b2);
            pa3 = make_float4(b3, b3, b3, b3);
#pragma unroll 4
            for (int h = 0; h < 64; h++) {
                float4 w = *(const float4*)&s.P2s[h][c20];
                float4 tv = *(const float4*)&s.th[h][e20];
                fma4(pa0, w.x, tv); fma4(pa1, w.y, tv);
                fma4(pa2, w.z, tv); fma4(pa3, w.w, tv);
            }
        }
        // ---- stage 2b (no barrier needed: th untouched, kgu elements are thread-private) ----
        float4 valv = *(const float4*)&s.vals[ptE][c20];
        {
            float q0 = s.qy[ptE][c20], q1 = s.qy[ptE][c20 + 1];
            float q2 = s.qy[ptE][c20 + 2], q3 = s.qy[ptE][c20 + 3];
            float4 k0 = *(const float4*)&s.kgu[c20][e20];
            float4 k1 = *(const float4*)&s.kgu[c20 + 1][e20];
            float4 k2 = *(const float4*)&s.kgu[c20 + 2][e20];
            float4 k3 = *(const float4*)&s.kgu[c20 + 3][e20];
            float4 u;
            u.x = (q0 - k0.x) + pa0.x; u.y = (q0 - k0.y) + pa0.y;
            u.z = (q0 - k0.z) + pa0.z; u.w = (q0 - k0.w) + pa0.w;
            *(float4*)&s.kgu[c20][e20] = u;
            u.x = (q1 - k1.x) + pa1.x; u.y = (q1 - k1.y) + pa1.y;
            u.z = (q1 - k1.z) + pa1.z; u.w = (q1 - k1.w) + pa1.w;
            *(float4*)&s.kgu[c20 + 1][e20] = u;
            u.x = (q2 - k2.x) + pa2.x; u.y = (q2 - k2.y) + pa2.y;
            u.z = (q2 - k2.z) + pa2.z; u.w = (q2 - k2.w) + pa2.w;
            *(float4*)&s.kgu[c20 + 2][e20] = u;
            u.x = (q3 - k3.x) + pa3.x; u.y = (q3 - k3.y) + pa3.y;
            u.z = (q3 - k3.z) + pa3.z; u.w = (q3 - k3.w) + pa3.w;
            *(float4*)&s.kgu[c20 + 3][e20] = u;
        }
        __syncthreads();   // sync2

        // ---- stages 4+5 over two h-halves; logits accumulate in regs ----
        float4 L0, L1, L2, L3;
        {
            float b0 = s.ab2s[c20], b1 = s.ab2s[c20 + 1], b2 = s.ab2s[c20 + 2], b3 = s.ab2s[c20 + 3];
            L0 = make_float4(b0, b0, b0, b0);
            L1 = make_float4(b1, b1, b1, b1);
            L2 = make_float4(b2, b2, b2, b2);
            L3 = make_float4(b3, b3, b3, b3);
        }
#pragma unroll
        for (int r = 0; r < 2; r++) {
            {
                int abase = r * 128 + a0r;
                float b0 = s.b1p[abase], b1 = s.b1p[abase + 1];
                float b2 = s.b1p[abase + 2], b3 = s.b1p[abase + 3];
                float4 A00 = make_float4(b0, b0, b0, b0), A01 = A00;
                float4 A10 = make_float4(b1, b1, b1, b1), A11 = A10;
                float4 A20 = make_float4(b2, b2, b2, b2), A21 = A20;
                float4 A30 = make_float4(b3, b3, b3, b3), A31 = A30;
#pragma unroll 4
                for (int c = 0; c < 64; c++) {
                    float4 w = *(const float4*)&s.A1s[c][abase];
                    float4 u0 = *(const float4*)&s.kgu[c][e40];
                    float4 u1 = *(const float4*)&s.kgu[c][e40 + 4];
                    fma4(A00, w.x, u0); fma4(A01, w.x, u1);
                    fma4(A10, w.y, u0); fma4(A11, w.y, u1);
                    fma4(A20, w.z, u0); fma4(A21, w.z, u1);
                    fma4(A30, w.w, u0); fma4(A31, w.w, u1);
                }
#define RELU4(v) v.x = fmaxf(v.x, 0.f); v.y = fmaxf(v.y, 0.f); v.z = fmaxf(v.z, 0.f); v.w = fmaxf(v.w, 0.f);
                RELU4(A00) RELU4(A01) RELU4(A10) RELU4(A11)
                RELU4(A20) RELU4(A21) RELU4(A30) RELU4(A31)
#undef RELU4
                *(float4*)&s.h1s[a0r][e40] = A00;     *(float4*)&s.h1s[a0r][e40 + 4] = A01;
                *(float4*)&s.h1s[a0r + 1][e40] = A10; *(float4*)&s.h1s[a0r + 1][e40 + 4] = A11;
                *(float4*)&s.h1s[a0r + 2][e40] = A20; *(float4*)&s.h1s[a0r + 2][e40 + 4] = A21;
                *(float4*)&s.h1s[a0r + 3][e40] = A30; *(float4*)&s.h1s[a0r + 3][e40 + 4] = A31;
            }
            __syncthreads();
#pragma unroll 4
            for (int j = 0; j < 128; j++) {
                float4 w = *(const float4*)&s.A2s[r * 128 + j][c20];
                float4 hv = *(const float4*)&s.h1s[j][e20];
                fma4(L0, w.x, hv); fma4(L1, w.y, hv);
                fma4(L2, w.z, hv); fma4(L3, w.w, hv);
            }
            if (r == 0) __syncthreads();
            // (r=1: next-iter sync0/1/2 order h1s reads before overwrite)
        }

        // ---- epilogue: softmax over k (4-lane groups) + aggregate, pure registers ----
        {
            float m0 = fmaxf(fmaxf(L0.x, L0.y), fmaxf(L0.z, L0.w));
            float m1 = fmaxf(fmaxf(L1.x, L1.y), fmaxf(L1.z, L1.w));
            float m2 = fmaxf(fmaxf(L2.x, L2.y), fmaxf(L2.z, L2.w));
            float m3 = fmaxf(fmaxf(L3.x, L3.y), fmaxf(L3.z, L3.w));
            m0 = fmaxf(m0, __shfl_xor_sync(0xFFFFFFFFu, m0, 1));
            m0 = fmaxf(m0, __shfl_xor_sync(0xFFFFFFFFu, m0, 2));
            m1 = fmaxf(m1, __shfl_xor_sync(0xFFFFFFFFu, m1, 1));
            m1 = fmaxf(m1, __shfl_xor_sync(0xFFFFFFFFu, m1, 2));
            m2 = fmaxf(m2, __shfl_xor_sync(0xFFFFFFFFu, m2, 1));
            m2 = fmaxf(m2, __shfl_xor_sync(0xFFFFFFFFu, m2, 2));
            m3 = fmaxf(m3, __shfl_xor_sync(0xFFFFFFFFu, m3, 1));
            m3 = fmaxf(m3, __shfl_xor_sync(0xFFFFFFFFu, m3, 2));

            float e00 = __expf(L0.x - m0), e01 = __expf(L0.y - m0), e02 = __expf(L0.z - m0), e03 = __expf(L0.w - m0);
            float e10 = __expf(L1.x - m1), e11 = __expf(L1.y - m1), e12 = __expf(L1.z - m1), e13 = __expf(L1.w - m1);
            float e20_ = __expf(L2.x - m2), e21 = __expf(L2.y - m2), e22 = __expf(L2.z - m2), e23 = __expf(L2.w - m2);
            float e30 = __expf(L3.x - m3), e31 = __expf(L3.y - m3), e32 = __expf(L3.z - m3), e33 = __expf(L3.w - m3);

            float s0 = e00 + e01 + e02 + e03;
            float s1 = e10 + e11 + e12 + e13;
            float s2 = e20_ + e21 + e22 + e23;
            float s3 = e30 + e31 + e32 + e33;
            float a0 = e00 * pa0.x + e01 * pa0.y + e02 * pa0.z + e03 * pa0.w;
            float a1 = e10 * pa1.x + e11 * pa1.y + e12 * pa1.z + e13 * pa1.w;
            float a2 = e20_ * pa2.x + e21 * pa2.y + e22 * pa2.z + e23 * pa2.w;
            float a3 = e30 * pa3.x + e31 * pa3.y + e32 * pa3.z + e33 * pa3.w;

            s0 += __shfl_xor_sync(0xFFFFFFFFu, s0, 1); s0 += __shfl_xor_sync(0xFFFFFFFFu, s0, 2);
            s1 += __shfl_xor_sync(0xFFFFFFFFu, s1, 1); s1 += __shfl_xor_sync(0xFFFFFFFFu, s1, 2);
            s2 += __shfl_xor_sync(0xFFFFFFFFu, s2, 1); s2 += __shfl_xor_sync(0xFFFFFFFFu, s2, 2);
            s3 += __shfl_xor_sync(0xFFFFFFFFu, s3, 1); s3 += __shfl_xor_sync(0xFFFFFFFFu, s3, 2);
            a0 += __shfl_xor_sync(0xFFFFFFFFu, a0, 1); a0 += __shfl_xor_sync(0xFFFFFFFFu, a0, 2);
            a1 += __shfl_xor_sync(0xFFFFFFFFu, a1, 1); a1 += __shfl_xor_sync(0xFFFFFFFFu, a1, 2);
            a2 += __shfl_xor_sync(0xFFFFFFFFu, a2, 1); a2 += __shfl_xor_sync(0xFFFFFFFFu, a2, 2);
            a3 += __shfl_xor_sync(0xFFFFFFFFu, a3, 1); a3 += __shfl_xor_sync(0xFFFFFFFFu, a3, 2);

            if ((t & 3) == 0) {
                float4 o = make_float4(valv.x + a0 / s0, valv.y + a1 / s1,
                                       valv.z + a2 / s2, valv.w + a3 / s3);
                *(float4*)&g_agg[((size_t)b * NN + n0 + ptE) * CC + c20] = o;
            }
        }
        // no loop-end barrier: next-iter sync0 orders all smem reuse
    }
}

// ================= Kernel 4: out = W_end @ agg + b_end + y =================
__global__ __launch_bounds__(256) void k_end(
    const float* __restrict__ y, const float* __restrict__ We_g,
    const float* __restrict__ be_g, float* __restrict__ out)
{
    __shared__ float As[64][65];
    __shared__ float Ws[64][64];
    int b = blockIdx.y, n0 = blockIdx.x * 64, t = threadIdx.x;
#pragma unroll
    for (int i = 0; i < 16; i++) { int e = t + i * 256; Ws[e >> 6][e & 63] = We_g[e]; }
#pragma unroll
    for (int i = 0; i < 16; i++) {
        int e = t + i * 256; int p = e >> 6, c = e & 63;
        As[p][c] = g_agg[((size_t)b * NN + n0 + p) * CC + c];
    }
    __syncthreads();
    int p = t & 63, og = t >> 6;
    float acc[16];
#pragma unroll
    for (int i = 0; i < 16; i++) acc[i] = be_g[og * 16 + i];
#pragma unroll 4
    for (int c = 0; c < 64; c++) {
        float av = As[p][c];
#pragma unroll
        for (int i = 0; i < 16; i++) acc[i] = fmaf(Ws[og * 16 + i][c], av, acc[i]);
    }
#pragma unroll
    for (int i = 0; i < 16; i++) {
        int o = og * 16 + i;
        size_t off = ((size_t)b * CC + o) * NN + n0 + p;
        out[off] = acc[i] + y[off];
    }
}

// ================= launcher =================
extern "C" void kernel_launch(void* const* d_in, const int* in_sizes, int n_in,
                              void* d_out, int out_size)
{
    const float* x       = (const float*)d_in[0];
    const float* y       = (const float*)d_in[1];
    const float* W_start = (const float*)d_in[2];
    const float* b_start = (const float*)d_in[3];
    const float* W_key   = (const float*)d_in[4];
    const float* b_key   = (const float*)d_in[5];
    const float* W_query = (const float*)d_in[6];
    const float* b_query = (const float*)d_in[7];
    const float* P1      = (const float*)d_in[8];
    const float* pb1     = (const float*)d_in[9];
    const float* bn1_g   = (const float*)d_in[10];
    const float* bn1_b   = (const float*)d_in[11];
    const float* bn1_m   = (const float*)d_in[12];
    const float* bn1_v   = (const float*)d_in[13];
    const float* P2      = (const float*)d_in[14];
    const float* pb2     = (const float*)d_in[15];
    const float* A1      = (const float*)d_in[16];
    const float* ab1     = (const float*)d_in[17];
    const float* bn2_g   = (const float*)d_in[18];
    const float* bn2_b   = (const float*)d_in[19];
    const float* bn2_m   = (const float*)d_in[20];
    const float* bn2_v   = (const float*)d_in[21];
    const float* A2      = (const float*)d_in[22];
    const float* ab2     = (const float*)d_in[23];
    const float* W_end   = (const float*)d_in[24];
    const float* b_end   = (const float*)d_in[25];

    cudaFuncSetAttribute(k_attn, cudaFuncAttributeMaxDynamicSharedMemorySize, (int)sizeof(S3));

    k_dummy<<<1, 32>>>();
    k_linear_start_key<<<dim3(NN / 64, BB), 256>>>(y, W_start, b_start, W_key, b_key);
    k_knn_part<<<dim3(NN / 64, NSPL, BB), 64>>>(x);
    k_knn_merge<<<BB * NN / 128, 128>>>();
    k_attn<<<148, 256, sizeof(S3)>>>(x, W_query, b_query,
                                     P1, pb1, bn1_g, bn1_b, bn1_m, bn1_v,
                                     P2, pb2, A1, ab1,
                                     bn2_g, bn2_b, bn2_m, bn2_v, A2, ab2);
    k_end<<<dim3(NN / 64, BB), 256>>>(y, W_end, b_end, (float*)d_out);
}

// round 8
// speedup vs baseline: 2.1845x; 1.0690x over previous
#include <cuda_runtime.h>
#include <math.h>

#define BB 4
#define CC 64
#define NN 4096
#define KK 16
#define NSPL 2

// ---------------- scratch (no allocations allowed) ----------------
__device__ float g_val_t[BB * NN * CC];   // y1 (value), layout (B,N,C)
__device__ float g_key_t[BB * NN * CC];   // key, layout (B,N,C)
__device__ float g_agg[BB * NN * CC];     // aggregated features, layout (B,N,C)
__device__ int   g_idx[BB * NN * KK];     // knn indices (final)
__device__ float g_knn_d[BB][NSPL][NN][KK];
__device__ int   g_knn_i[BB][NSPL][NN][KK];

typedef unsigned long long ull;

__device__ __forceinline__ void fma4(float4& a, float w, const float4 v) {
    a.x = fmaf(w, v.x, a.x);
    a.y = fmaf(w, v.y, a.y);
    a.z = fmaf(w, v.z, a.z);
    a.w = fmaf(w, v.w, a.w);
}
// -------- packed f32x2 helpers (bitwise-identical IEEE fp32 lanes) --------
__device__ __forceinline__ ull bcast2(float v) {
    ull r; asm("mov.b64 %0, {%1, %1};" : "=l"(r) : "f"(v)); return r;
}
__device__ __forceinline__ void ffma2(ull& d, ull a, ull b) {
    asm("fma.rn.f32x2 %0, %1, %2, %0;" : "+l"(d) : "l"(a), "l"(b));
}
__device__ __forceinline__ void f4_to_p(const float4 v, ull& lo, ull& hi) {
    asm("mov.b64 %0, {%2, %3};\n\tmov.b64 %1, {%4, %5};"
        : "=l"(lo), "=l"(hi) : "f"(v.x), "f"(v.y), "f"(v.z), "f"(v.w));
}
__device__ __forceinline__ float4 p_to_f4(ull lo, ull hi) {
    float4 v;
    asm("mov.b64 {%0, %1}, %4;\n\tmov.b64 {%2, %3}, %5;"
        : "=f"(v.x), "=f"(v.y), "=f"(v.z), "=f"(v.w) : "l"(lo), "l"(hi));
    return v;
}

// ================= Kernel 1: y1 = W_start@y+b ; key = W_key@y1+b (written transposed (B,N,C)) =================
__global__ __launch_bounds__(256) void k_linear_start_key(
    const float* __restrict__ y,
    const float* __restrict__ Ws_g, const float* __restrict__ bs_g,
    const float* __restrict__ Wk_g, const float* __restrict__ bk_g)
{
    __shared__ float ys[64][64];
    __shared__ float y1s[64][64];
    __shared__ float Ws[64][64];
    int b = blockIdx.y, n0 = blockIdx.x * 64, t = threadIdx.x;

#pragma unroll
    for (int i = 0; i < 16; i++) { int e = t + i * 256; Ws[e >> 6][e & 63] = Ws_g[e]; }
#pragma unroll
    for (int i = 0; i < 16; i++) {
        int e = t + i * 256; int c = e >> 6, p = e & 63;
        ys[c][p] = y[((size_t)b * CC + c) * NN + n0 + p];
    }
    __syncthreads();

    int p = t & 63, og = t >> 6;
    float acc[16];
#pragma unroll
    for (int i = 0; i < 16; i++) acc[i] = bs_g[og * 16 + i];
#pragma unroll 4
    for (int c = 0; c < 64; c++) {
        float yv = ys[c][p];
#pragma unroll
        for (int i = 0; i < 16; i++) acc[i] = fmaf(Ws[og * 16 + i][c], yv, acc[i]);
    }
#pragma unroll
    for (int i = 0; i < 16; i++) y1s[og * 16 + i][p] = acc[i];
    {
        float4* vo = (float4*)&g_val_t[(((size_t)b * NN) + n0 + p) * CC + og * 16];
        vo[0] = make_float4(acc[0], acc[1], acc[2], acc[3]);
        vo[1] = make_float4(acc[4], acc[5], acc[6], acc[7]);
        vo[2] = make_float4(acc[8], acc[9], acc[10], acc[11]);
        vo[3] = make_float4(acc[12], acc[13], acc[14], acc[15]);
    }
    __syncthreads();
#pragma unroll
    for (int i = 0; i < 16; i++) { int e = t + i * 256; Ws[e >> 6][e & 63] = Wk_g[e]; }
    __syncthreads();
#pragma unroll
    for (int i = 0; i < 16; i++) acc[i] = bk_g[og * 16 + i];
#pragma unroll 4
    for (int c = 0; c < 64; c++) {
        float yv = y1s[c][p];
#pragma unroll
        for (int i = 0; i < 16; i++) acc[i] = fmaf(Ws[og * 16 + i][c], yv, acc[i]);
    }
    {
        float4* ko = (float4*)&g_key_t[(((size_t)b * NN) + n0 + p) * CC + og * 16];
        ko[0] = make_float4(acc[0], acc[1], acc[2], acc[3]);
        ko[1] = make_float4(acc[4], acc[5], acc[6], acc[7]);
        ko[2] = make_float4(acc[8], acc[9], acc[10], acc[11]);
        ko[3] = make_float4(acc[12], acc[13], acc[14], acc[15]);
    }
}

// ================= Kernel 2a: KNN partial (candidate-split, d' = ssq - 2*dot ordering) =================
__global__ __launch_bounds__(64) void k_knn_part(const float* __restrict__ x)
{
    __shared__ float4 cand[64];
    int b = blockIdx.z, sp = blockIdx.y;
    int i = blockIdx.x * 64 + threadIdx.x;
    const float* xb = x + (size_t)b * 3 * NN;
    float qx = xb[i], qy = xb[NN + i], qz = xb[2 * NN + i];

    float bd[16]; int bi[16];
#pragma unroll
    for (int s = 0; s < 16; s++) { bd[s] = 3.0e38f; bi[s] = 0; }

    int base = sp * (NN / NSPL);
    for (int c0 = 0; c0 < NN / NSPL; c0 += 64) {
        int j = base + c0 + threadIdx.x;
        float ax = xb[j], ay = xb[NN + j], az = xb[2 * NN + j];
        cand[threadIdx.x] = make_float4(ax, ay, az, ax * ax + ay * ay + az * az);
        __syncthreads();
        for (int jj = 0; jj < 64; jj++) {
            float4 cv = cand[jj];
            float dot = qx * cv.x + qy * cv.y + qz * cv.z;
            float d = fmaf(-2.0f, dot, cv.w);
            if (d < bd[15]) {
                bd[15] = d; bi[15] = base + c0 + jj;
#pragma unroll
                for (int s = 15; s > 0; --s) {
                    if (bd[s] < bd[s - 1]) {
                        float td = bd[s]; bd[s] = bd[s - 1]; bd[s - 1] = td;
                        int ti = bi[s]; bi[s] = bi[s - 1]; bi[s - 1] = ti;
                    } else break;
                }
            }
        }
        __syncthreads();
    }
#pragma unroll
    for (int s = 0; s < 16; s++) { g_knn_d[b][sp][i][s] = bd[s]; g_knn_i[b][sp][i][s] = bi[s]; }
}

// ================= Kernel 2b: merge the NSPL sorted partial lists =================
__global__ __launch_bounds__(128) void k_knn_merge()
{
    int g = blockIdx.x * 128 + threadIdx.x;
    int b = g >> 12, n = g & (NN - 1);
    float bd[16]; int bi[16];
#pragma unroll
    for (int s = 0; s < 16; s++) { bd[s] = g_knn_d[b][0][n][s]; bi[s] = g_knn_i[b][0][n][s]; }
    for (int s = 0; s < 16; s++) {
        float d = g_knn_d[b][1][n][s];
        if (d >= bd[15]) break;     // sorted ascending
        bd[15] = d; bi[15] = g_knn_i[b][1][n][s];
#pragma unroll
        for (int u = 15; u > 0; --u) {
            if (bd[u] < bd[u - 1]) {
                float td = bd[u]; bd[u] = bd[u - 1]; bd[u - 1] = td;
                int ti = bi[u]; bi[u] = bi[u - 1]; bi[u - 1] = ti;
            } else break;
        }
    }
#pragma unroll
    for (int s = 0; s < 16; s++) g_idx[((size_t)b * NN + n) * KK + s] = bi[s];
}

// ================= Kernel 3: fused attention, persistent blocks, FFMA2 mainloops =================
struct __align__(16) S3 {
    float A1s[64][260];     // [c][a], BN-folded A1
    float A2s[256][68];     // [h][c]
    float P2s[64][68];      // [h][c]
    float h1s[128][68];     // one h-half of h1
    float th[64][68];       // P1-hidden [h][e]
    float kgu[64][68];      // key [c][e] -> u [c][e]
    float P1p[64][3];
    float Wq[64][3];
    float b1p[256];
    float s2s[256];
    float s1s[64];
    float pb1p[64];
    float pb2s[64];
    float ab2s[64];
    float bqs[64];
    float posr[4][3][16];
    float qy[4][64];
    float vals[4][64];
};

#define NTILES (BB * NN / 4)   // 4096 tiles of 4 points

__global__ void __launch_bounds__(256, 1) k_attn(
    const float* __restrict__ x,
    const float* __restrict__ Wq_g, const float* __restrict__ bq_g,
    const float* __restrict__ P1, const float* __restrict__ pb1,
    const float* __restrict__ bn1_g, const float* __restrict__ bn1_b,
    const float* __restrict__ bn1_m, const float* __restrict__ bn1_v,
    const float* __restrict__ P2, const float* __restrict__ pb2,
    const float* __restrict__ A1, const float* __restrict__ ab1,
    const float* __restrict__ bn2_g, const float* __restrict__ bn2_b,
    const float* __restrict__ bn2_m, const float* __restrict__ bn2_v,
    const float* __restrict__ A2, const float* __restrict__ ab2)
{
    extern __shared__ char smraw[];
    S3& s = *(S3*)smraw;
    int t = threadIdx.x;

    // ---- fold BN into weights/biases (once per persistent block) ----
    {
        float s2 = bn2_g[t] / sqrtf(bn2_v[t] + 1e-5f);
        s.s2s[t] = s2;
        s.b1p[t] = (ab1[t] - bn2_m[t]) * s2 + bn2_b[t];
    }
    if (t < 64) {
        float s1 = bn1_g[t] / sqrtf(bn1_v[t] + 1e-5f);
        s.s1s[t] = s1;
        s.pb1p[t] = (pb1[t] - bn1_m[t]) * s1 + bn1_b[t];
        s.pb2s[t] = pb2[t];
        s.ab2s[t] = ab2[t];
        s.bqs[t] = bq_g[t];
    }
    if (t < 192) s.Wq[t / 3][t % 3] = Wq_g[t];
    __syncthreads();
    if (t < 192) s.P1p[t / 3][t % 3] = P1[t] * s.s1s[t / 3];
#pragma unroll
    for (int i = 0; i < 64; i++) {
        int e = t + i * 256; int a = e >> 6, c = e & 63;
        s.A1s[c][a] = A1[e] * s.s2s[a];
    }
#pragma unroll
    for (int i = 0; i < 64; i++) {
        int e = t + i * 256; int c = e >> 8, h = e & 255;
        s.A2s[h][c] = A2[e];
    }
#pragma unroll
    for (int i = 0; i < 16; i++) {
        int e = t + i * 256; int c = e >> 6, h = e & 63;
        s.P2s[h][c] = P2[e];
    }
    __syncthreads();

    // per-thread stage identities
    const int cg2 = t >> 4, eg2 = t & 15;         // stage 2/5: 4c x 4e tile
    const int c20 = cg2 * 4, e20 = eg2 * 4;
    const int ag = t >> 3, eg4 = t & 7;           // stage 4: 4a x 8e tile
    const int a0r = ag * 4, e40 = eg4 * 8;
    const int pt6 = t >> 6, c6 = t & 63;          // stage 0b: (pt, c)
    const int ptE = e20 >> 4;                     // epilogue point

    for (int tile = blockIdx.x; tile < NTILES; tile += gridDim.x) {
        int b = tile >> 10;
        int n0 = (tile & 1023) * 4;
        const float* xb = x + (size_t)b * 3 * NN;
        const int* idxb = &g_idx[(size_t)b * NN * KK];

        // ---- stage 0: key gather (kgu <- key), posr, qy, vals ----
        {
            int e = t & 63, cq = t >> 6;
            int pt = e >> 4, k = e & 15;
            int j = idxb[(n0 + pt) * KK + k];
            const float4* kp = (const float4*)&g_key_t[((size_t)b * NN + j) * CC + cq * 16];
            float4 v0 = kp[0], v1 = kp[1], v2 = kp[2], v3 = kp[3];
            int cb = cq * 16;
            s.kgu[cb + 0][e] = v0.x;  s.kgu[cb + 1][e] = v0.y;
            s.kgu[cb + 2][e] = v0.z;  s.kgu[cb + 3][e] = v0.w;
            s.kgu[cb + 4][e] = v1.x;  s.kgu[cb + 5][e] = v1.y;
            s.kgu[cb + 6][e] = v1.z;  s.kgu[cb + 7][e] = v1.w;
            s.kgu[cb + 8][e] = v2.x;  s.kgu[cb + 9][e] = v2.y;
            s.kgu[cb + 10][e] = v2.z; s.kgu[cb + 11][e] = v2.w;
            s.kgu[cb + 12][e] = v3.x; s.kgu[cb + 13][e] = v3.y;
            s.kgu[cb + 14][e] = v3.z; s.kgu[cb + 15][e] = v3.w;
        }
        if (t < 192) {
            int pt = t / 48, r = t % 48, d = r >> 4, k = r & 15;
            int j = idxb[(n0 + pt) * KK + k];
            s.posr[pt][d][k] = xb[d * NN + n0 + pt] - xb[d * NN + j];
        }
        {
            int n = n0 + pt6;
            s.qy[pt6][c6] = s.bqs[c6] + s.Wq[c6][0] * xb[n] + s.Wq[c6][1] * xb[NN + n]
                          + s.Wq[c6][2] * xb[2 * NN + n];
            s.vals[pt6][c6] = g_val_t[((size_t)b * NN + n) * CC + c6];
        }
        __syncthreads();   // sync0

        // ---- stage 1: th[h][e] = relu(P1'@pos_rel + pb1') ----
        {
            int h = t & 63, pt = t >> 6;
            float p0 = s.P1p[h][0], p1 = s.P1p[h][1], p2 = s.P1p[h][2], bb = s.pb1p[h];
#pragma unroll
            for (int g = 0; g < 4; g++) {
                float4 o;
                float* ov = (float*)&o;
#pragma unroll
                for (int kk = 0; kk < 4; kk++) {
                    int k = g * 4 + kk;
                    float a = bb + p0 * s.posr[pt][0][k] + p1 * s.posr[pt][1][k]
                                 + p2 * s.posr[pt][2][k];
                    ov[kk] = fmaxf(a, 0.0f);
                }
                *(float4*)&s.th[h][pt * 16 + g * 4] = o;
            }
        }
        __syncthreads();   // sync1

        // ---- stage 2: pe = P2@th + pb2 (FFMA2 pairs, kept in registers) ----
        float4 pa0, pa1, pa2, pa3;
        {
            ull P0l, P0h, P1l, P1h, P2l, P2h, P3l, P3h;
            P0l = P0h = bcast2(s.pb2s[c20]);
            P1l = P1h = bcast2(s.pb2s[c20 + 1]);
            P2l = P2h = bcast2(s.pb2s[c20 + 2]);
            P3l = P3h = bcast2(s.pb2s[c20 + 3]);
#pragma unroll 4
            for (int h = 0; h < 64; h++) {
                float4 w = *(const float4*)&s.P2s[h][c20];
                float4 tv = *(const float4*)&s.th[h][e20];
                ull tl, thh; f4_to_p(tv, tl, thh);
                ull wx = bcast2(w.x), wy = bcast2(w.y), wz = bcast2(w.z), ww = bcast2(w.w);
                ffma2(P0l, wx, tl); ffma2(P0h, wx, thh);
                ffma2(P1l, wy, tl); ffma2(P1h, wy, thh);
                ffma2(P2l, wz, tl); ffma2(P2h, wz, thh);
                ffma2(P3l, ww, tl); ffma2(P3h, ww, thh);
            }
            pa0 = p_to_f4(P0l, P0h); pa1 = p_to_f4(P1l, P1h);
            pa2 = p_to_f4(P2l, P2h); pa3 = p_to_f4(P3l, P3h);
        }
        // ---- stage 2b (no barrier: th untouched, kgu elements thread-private) ----
        float4 valv = *(const float4*)&s.vals[ptE][c20];
        {
            float q0 = s.qy[ptE][c20], q1 = s.qy[ptE][c20 + 1];
            float q2 = s.qy[ptE][c20 + 2], q3 = s.qy[ptE][c20 + 3];
            float4 k0 = *(const float4*)&s.kgu[c20][e20];
            float4 k1 = *(const float4*)&s.kgu[c20 + 1][e20];
            float4 k2 = *(const float4*)&s.kgu[c20 + 2][e20];
            float4 k3 = *(const float4*)&s.kgu[c20 + 3][e20];
            float4 u;
            u.x = (q0 - k0.x) + pa0.x; u.y = (q0 - k0.y) + pa0.y;
            u.z = (q0 - k0.z) + pa0.z; u.w = (q0 - k0.w) + pa0.w;
            *(float4*)&s.kgu[c20][e20] = u;
            u.x = (q1 - k1.x) + pa1.x; u.y = (q1 - k1.y) + pa1.y;
            u.z = (q1 - k1.z) + pa1.z; u.w = (q1 - k1.w) + pa1.w;
            *(float4*)&s.kgu[c20 + 1][e20] = u;
            u.x = (q2 - k2.x) + pa2.x; u.y = (q2 - k2.y) + pa2.y;
            u.z = (q2 - k2.z) + pa2.z; u.w = (q2 - k2.w) + pa2.w;
            *(float4*)&s.kgu[c20 + 2][e20] = u;
            u.x = (q3 - k3.x) + pa3.x; u.y = (q3 - k3.y) + pa3.y;
            u.z = (q3 - k3.z) + pa3.z; u.w = (q3 - k3.w) + pa3.w;
            *(float4*)&s.kgu[c20 + 3][e20] = u;
        }
        __syncthreads();   // sync2

        // ---- stages 4+5 over two h-halves; logits accumulate in FFMA2 pairs ----
        ull L0l, L0h, L1l, L1h, L2l, L2h, L3l, L3h;
        L0l = L0h = bcast2(s.ab2s[c20]);
        L1l = L1h = bcast2(s.ab2s[c20 + 1]);
        L2l = L2h = bcast2(s.ab2s[c20 + 2]);
        L3l = L3h = bcast2(s.ab2s[c20 + 3]);
#pragma unroll
        for (int r = 0; r < 2; r++) {
            // stage 4: h1[half] = relu(A1'@u + b1')  (4a x 8e tile, FFMA2)
            {
                int abase = r * 128 + a0r;
                ull A0[4], A1p[4], A2p[4], A3p[4];   // [a][pair: u0lo,u0hi,u1lo,u1hi]
                {
                    ull b0 = bcast2(s.b1p[abase]),     b1 = bcast2(s.b1p[abase + 1]);
                    ull b2 = bcast2(s.b1p[abase + 2]), b3 = bcast2(s.b1p[abase + 3]);
#pragma unroll
                    for (int g = 0; g < 4; g++) { A0[g] = b0; A1p[g] = b1; A2p[g] = b2; A3p[g] = b3; }
                }
#pragma unroll 4
                for (int c = 0; c < 64; c++) {
                    float4 w = *(const float4*)&s.A1s[c][abase];
                    float4 u0 = *(const float4*)&s.kgu[c][e40];
                    float4 u1 = *(const float4*)&s.kgu[c][e40 + 4];
                    ull u0l, u0h, u1l, u1h;
                    f4_to_p(u0, u0l, u0h); f4_to_p(u1, u1l, u1h);
                    ull wx = bcast2(w.x), wy = bcast2(w.y), wz = bcast2(w.z), ww = bcast2(w.w);
                    ffma2(A0[0], wx, u0l);  ffma2(A0[1], wx, u0h);
                    ffma2(A0[2], wx, u1l);  ffma2(A0[3], wx, u1h);
                    ffma2(A1p[0], wy, u0l); ffma2(A1p[1], wy, u0h);
                    ffma2(A1p[2], wy, u1l); ffma2(A1p[3], wy, u1h);
                    ffma2(A2p[0], wz, u0l); ffma2(A2p[1], wz, u0h);
                    ffma2(A2p[2], wz, u1l); ffma2(A2p[3], wz, u1h);
                    ffma2(A3p[0], ww, u0l); ffma2(A3p[1], ww, u0h);
                    ffma2(A3p[2], ww, u1l); ffma2(A3p[3], ww, u1h);
                }
#define ST_RELU(pairs, row)                                                     \
                {                                                               \
                    float4 v0 = p_to_f4(pairs[0], pairs[1]);                    \
                    float4 v1 = p_to_f4(pairs[2], pairs[3]);                    \
                    v0.x = fmaxf(v0.x, 0.f); v0.y = fmaxf(v0.y, 0.f);           \
                    v0.z = fmaxf(v0.z, 0.f); v0.w = fmaxf(v0.w, 0.f);           \
                    v1.x = fmaxf(v1.x, 0.f); v1.y = fmaxf(v1.y, 0.f);           \
                    v1.z = fmaxf(v1.z, 0.f); v1.w = fmaxf(v1.w, 0.f);           \
                    *(float4*)&s.h1s[row][e40] = v0;                            \
                    *(float4*)&s.h1s[row][e40 + 4] = v1;                        \
                }
                ST_RELU(A0, a0r) ST_RELU(A1p, a0r + 1) ST_RELU(A2p, a0r + 2) ST_RELU(A3p, a0r + 3)
#undef ST_RELU
            }
            __syncthreads();
            // stage 5 partial: logits += A2[:, half]@h1[half]  (4c x 4e, FFMA2)
#pragma unroll 4
            for (int j = 0; j < 128; j++) {
                float4 w = *(const float4*)&s.A2s[r * 128 + j][c20];
                float4 hv = *(const float4*)&s.h1s[j][e20];
                ull hl, hh; f4_to_p(hv, hl, hh);
                ull wx = bcast2(w.x), wy = bcast2(w.y), wz = bcast2(w.z), ww = bcast2(w.w);
                ffma2(L0l, wx, hl); ffma2(L0h, wx, hh);
                ffma2(L1l, wy, hl); ffma2(L1h, wy, hh);
                ffma2(L2l, wz, hl); ffma2(L2h, wz, hh);
                ffma2(L3l, ww, hl); ffma2(L3h, ww, hh);
            }
            if (r == 0) __syncthreads();
            // (r=1: next-iter sync0/1/2 order h1s reads before overwrite)
        }
        float4 L0 = p_to_f4(L0l, L0h), L1 = p_to_f4(L1l, L1h);
        float4 L2 = p_to_f4(L2l, L2h), L3 = p_to_f4(L3l, L3h);

        // ---- epilogue: softmax over k (4-lane groups) + aggregate, pure registers ----
        {
            float m0 = fmaxf(fmaxf(L0.x, L0.y), fmaxf(L0.z, L0.w));
            float m1 = fmaxf(fmaxf(L1.x, L1.y), fmaxf(L1.z, L1.w));
            float m2 = fmaxf(fmaxf(L2.x, L2.y), fmaxf(L2.z, L2.w));
            float m3 = fmaxf(fmaxf(L3.x, L3.y), fmaxf(L3.z, L3.w));
            m0 = fmaxf(m0, __shfl_xor_sync(0xFFFFFFFFu, m0, 1));
            m0 = fmaxf(m0, __shfl_xor_sync(0xFFFFFFFFu, m0, 2));
            m1 = fmaxf(m1, __shfl_xor_sync(0xFFFFFFFFu, m1, 1));
            m1 = fmaxf(m1, __shfl_xor_sync(0xFFFFFFFFu, m1, 2));
            m2 = fmaxf(m2, __shfl_xor_sync(0xFFFFFFFFu, m2, 1));
            m2 = fmaxf(m2, __shfl_xor_sync(0xFFFFFFFFu, m2, 2));
            m3 = fmaxf(m3, __shfl_xor_sync(0xFFFFFFFFu, m3, 1));
            m3 = fmaxf(m3, __shfl_xor_sync(0xFFFFFFFFu, m3, 2));

            float e00 = __expf(L0.x - m0), e01 = __expf(L0.y - m0), e02 = __expf(L0.z - m0), e03 = __expf(L0.w - m0);
            float e10 = __expf(L1.x - m1), e11 = __expf(L1.y - m1), e12 = __expf(L1.z - m1), e13 = __expf(L1.w - m1);
            float e20_ = __expf(L2.x - m2), e21 = __expf(L2.y - m2), e22 = __expf(L2.z - m2), e23 = __expf(L2.w - m2);
            float e30 = __expf(L3.x - m3), e31 = __expf(L3.y - m3), e32 = __expf(L3.z - m3), e33 = __expf(L3.w - m3);

            float s0 = e00 + e01 + e02 + e03;
            float s1 = e10 + e11 + e12 + e13;
            float s2 = e20_ + e21 + e22 + e23;
            float s3 = e30 + e31 + e32 + e33;
            float a0 = e00 * pa0.x + e01 * pa0.y + e02 * pa0.z + e03 * pa0.w;
            float a1 = e10 * pa1.x + e11 * pa1.y + e12 * pa1.z + e13 * pa1.w;
            float a2 = e20_ * pa2.x + e21 * pa2.y + e22 * pa2.z + e23 * pa2.w;
            float a3 = e30 * pa3.x + e31 * pa3.y + e32 * pa3.z + e33 * pa3.w;

            s0 += __shfl_xor_sync(0xFFFFFFFFu, s0, 1); s0 += __shfl_xor_sync(0xFFFFFFFFu, s0, 2);
            s1 += __shfl_xor_sync(0xFFFFFFFFu, s1, 1); s1 += __shfl_xor_sync(0xFFFFFFFFu, s1, 2);
            s2 += __shfl_xor_sync(0xFFFFFFFFu, s2, 1); s2 += __shfl_xor_sync(0xFFFFFFFFu, s2, 2);
            s3 += __shfl_xor_sync(0xFFFFFFFFu, s3, 1); s3 += __shfl_xor_sync(0xFFFFFFFFu, s3, 2);
            a0 += __shfl_xor_sync(0xFFFFFFFFu, a0, 1); a0 += __shfl_xor_sync(0xFFFFFFFFu, a0, 2);
            a1 += __shfl_xor_sync(0xFFFFFFFFu, a1, 1); a1 += __shfl_xor_sync(0xFFFFFFFFu, a1, 2);
            a2 += __shfl_xor_sync(0xFFFFFFFFu, a2, 1); a2 += __shfl_xor_sync(0xFFFFFFFFu, a2, 2);
            a3 += __shfl_xor_sync(0xFFFFFFFFu, a3, 1); a3 += __shfl_xor_sync(0xFFFFFFFFu, a3, 2);

            if ((t & 3) == 0) {
                float4 o = make_float4(valv.x + a0 / s0, valv.y + a1 / s1,
                                       valv.z + a2 / s2, valv.w + a3 / s3);
                *(float4*)&g_agg[((size_t)b * NN + n0 + ptE) * CC + c20] = o;
            }
        }
        // no loop-end barrier: next-iter sync0 orders all smem reuse
    }
}

// ================= Kernel 4: out = W_end @ agg + b_end + y =================
__global__ __launch_bounds__(256) void k_end(
    const float* __restrict__ y, const float* __restrict__ We_g,
    const float* __restrict__ be_g, float* __restrict__ out)
{
    __shared__ float As[64][65];
    __shared__ float Ws[64][64];
    int b = blockIdx.y, n0 = blockIdx.x * 64, t = threadIdx.x;
#pragma unroll
    for (int i = 0; i < 16; i++) { int e = t + i * 256; Ws[e >> 6][e & 63] = We_g[e]; }
#pragma unroll
    for (int i = 0; i < 16; i++) {
        int e = t + i * 256; int p = e >> 6, c = e & 63;
        As[p][c] = g_agg[((size_t)b * NN + n0 + p) * CC + c];
    }
    __syncthreads();
    int p = t & 63, og = t >> 6;
    float acc[16];
#pragma unroll
    for (int i = 0; i < 16; i++) acc[i] = be_g[og * 16 + i];
#pragma unroll 4
    for (int c = 0; c < 64; c++) {
        float av = As[p][c];
#pragma unroll
        for (int i = 0; i < 16; i++) acc[i] = fmaf(Ws[og * 16 + i][c], av, acc[i]);
    }
#pragma unroll
    for (int i = 0; i < 16; i++) {
        int o = og * 16 + i;
        size_t off = ((size_t)b * CC + o) * NN + n0 + p;
        out[off] = acc[i] + y[off];
    }
}

// ================= launcher (attn is 4th launch -> ncu -s 5 captures it) =================
extern "C" void kernel_launch(void* const* d_in, const int* in_sizes, int n_in,
                              void* d_out, int out_size)
{
    const float* x       = (const float*)d_in[0];
    const float* y       = (const float*)d_in[1];
    const float* W_start = (const float*)d_in[2];
    const float* b_start = (const float*)d_in[3];
    const float* W_key   = (const float*)d_in[4];
    const float* b_key   = (const float*)d_in[5];
    const float* W_query = (const float*)d_in[6];
    const float* b_query = (const float*)d_in[7];
    const float* P1      = (const float*)d_in[8];
    const float* pb1     = (const float*)d_in[9];
    const float* bn1_g   = (const float*)d_in[10];
    const float* bn1_b   = (const float*)d_in[11];
    const float* bn1_m   = (const float*)d_in[12];
    const float* bn1_v   = (const float*)d_in[13];
    const float* P2      = (const float*)d_in[14];
    const float* pb2     = (const float*)d_in[15];
    const float* A1      = (const float*)d_in[16];
    const float* ab1     = (const float*)d_in[17];
    const float* bn2_g   = (const float*)d_in[18];
    const float* bn2_b   = (const float*)d_in[19];
    const float* bn2_m   = (const float*)d_in[20];
    const float* bn2_v   = (const float*)d_in[21];
    const float* A2      = (const float*)d_in[22];
    const float* ab2     = (const float*)d_in[23];
    const float* W_end   = (const float*)d_in[24];
    const float* b_end   = (const float*)d_in[25];

    cudaFuncSetAttribute(k_attn, cudaFuncAttributeMaxDynamicSharedMemorySize, (int)sizeof(S3));

    k_linear_start_key<<<dim3(NN / 64, BB), 256>>>(y, W_start, b_start, W_key, b_key);
    k_knn_part<<<dim3(NN / 64, NSPL, BB), 64>>>(x);
    k_knn_merge<<<BB * NN / 128, 128>>>();
    k_attn<<<148, 256, sizeof(S3)>>>(x, W_query, b_query,
                                     P1, pb1, bn1_g, bn1_b, bn1_m, bn1_v,
                                     P2, pb2, A1, ab1,
                                     bn2_g, bn2_b, bn2_m, bn2_v, A2, ab2);
    k_end<<<dim3(NN / 64, BB), 256>>>(y, W_end, b_end, (float*)d_out);
}